// round 1
// baseline (speedup 1.0000x reference)
#include <cuda_runtime.h>
#include <math.h>

#define Bsz 8
#define Ssz 1024
#define Dsz 512
#define Hsz 8
#define DHsz 64
#define FFsz 1024
#define NPOS 64          // 2*SPAN
#define NROWS (Bsz*Ssz)  // 8192

// ---------------- scratch (device globals; no allocation allowed) ------------
__device__ float g_xn  [Bsz*Ssz*Dsz];
__device__ float g_conv[Bsz*Ssz*Dsz];
__device__ float g_x1  [Bsz*Ssz*Dsz];
__device__ float g_x2  [Bsz*Ssz*Dsz];
__device__ float g_q   [Bsz*Ssz*Dsz];
__device__ float g_k   [Bsz*Ssz*Dsz];
__device__ float g_v   [Bsz*Ssz*Dsz];
__device__ float g_ctx [Bsz*Ssz*Dsz];
__device__ float g_posk[NPOS*Dsz];
__device__ float g_posq[NPOS*Dsz];
__device__ float g_c2p [Bsz*Hsz*Ssz*NPOS];
__device__ float g_p2c [Bsz*Hsz*Ssz*NPOS];
__device__ float g_scores[(size_t)Bsz*Hsz*Ssz*Ssz];  // 256 MB
__device__ float g_ff  [Bsz*Ssz*FFsz];
__device__ int   g_lut [2*Ssz];

// ---------------- relative-position bucket LUT --------------------------------
__global__ void build_lut_kernel(int* __restrict__ lut) {
    int t = blockIdx.x * blockDim.x + threadIdx.x;
    if (t >= 2*Ssz - 1) return;
    int rel = t - (Ssz - 1);   // i - j
    const int mid = 16;        // BUCKETS/2
    int bucket;
    if (rel > -mid && rel < mid) {
        bucket = rel;
    } else {
        float absp = fabsf((float)rel);
        if (absp <= (float)mid) {
            bucket = rel;
        } else {
            float logp = ceilf(logf(absp / 16.0f) / logf(127.0f / 16.0f) * 15.0f) + 16.0f;
            bucket = (rel > 0 ? 1 : -1) * (int)logp;
        }
    }
    int idx = bucket + 32;
    idx = min(max(idx, 0), 63);
    lut[t] = idx;
}

// ---------------- LayerNorm (D=512, one block per row) ------------------------
__global__ void layernorm_kernel(const float* __restrict__ x,
                                 const float* __restrict__ g,
                                 const float* __restrict__ bb,
                                 float* __restrict__ out) {
    const float* xr = x + (size_t)blockIdx.x * Dsz;
    float* orow = out + (size_t)blockIdx.x * Dsz;
    int tid = threadIdx.x;  // 256
    float v0 = xr[tid], v1 = xr[tid + 256];
    float s = v0 + v1, ss = v0 * v0 + v1 * v1;
    __shared__ float r1[8], r2[8];
    #pragma unroll
    for (int o = 16; o; o >>= 1) {
        s  += __shfl_xor_sync(0xffffffffu, s, o);
        ss += __shfl_xor_sync(0xffffffffu, ss, o);
    }
    if ((tid & 31) == 0) { r1[tid >> 5] = s; r2[tid >> 5] = ss; }
    __syncthreads();
    float S1 = 0.f, S2 = 0.f;
    #pragma unroll
    for (int i = 0; i < 8; i++) { S1 += r1[i]; S2 += r2[i]; }
    float mean = S1 * (1.0f / Dsz);
    float var  = S2 * (1.0f / Dsz) - mean * mean;
    float rs = rsqrtf(var + 1e-5f);
    orow[tid]       = (v0 - mean) * rs * g[tid]       + bb[tid];
    orow[tid + 256] = (v1 - mean) * rs * g[tid + 256] + bb[tid + 256];
}

// ---------------- depthwise conv (K=3 along S) + bias + SiLU ------------------
__global__ void dwconv_silu_kernel(const float* __restrict__ xn,
                                   const float* __restrict__ w,
                                   const float* __restrict__ bias,
                                   float* __restrict__ out) {
    size_t idx = (size_t)blockIdx.x * blockDim.x + threadIdx.x;
    if (idx >= (size_t)Bsz * Ssz * Dsz) return;
    int d = (int)(idx % Dsz);
    int s = (int)((idx / Dsz) % Ssz);
    const float* base = xn + idx;
    float w0 = w[d * 3 + 0], w1 = w[d * 3 + 1], w2 = w[d * 3 + 2];
    float acc = bias[d] + base[0] * w1;
    if (s > 0)        acc += base[-Dsz] * w0;
    if (s < Ssz - 1)  acc += base[ Dsz] * w2;
    out[idx] = acc / (1.0f + expf(-acc)) ;  // silu
}

// ---------------- generic tiled TN GEMM core: C[m,n] = sum_k A[m,k]*W[n,k] ----
// 64x64 tile, 256 threads, each thread 4x4.  Rows padded (+4) to keep float4
// alignment while killing smem store bank conflicts.
#define TK 16
#define TPAD 68

// EPI: 0=none, 1=+bias, 2=+bias+res, 3=silu(+bias)
template<int EPI>
__device__ __forceinline__ void gemm_tile_tn(
    const float* __restrict__ A, int lda,
    const float* __restrict__ W, int ldw,
    const float* __restrict__ bias,
    const float* __restrict__ res,
    float* __restrict__ C, int ldc,
    int m0, int n0, int Kd,
    float acc[4][4])
{
    __shared__ float As[TK][TPAD];
    __shared__ float Ws[TK][TPAD];
    const int tid = threadIdx.x;
    const int tx = tid & 15, ty = tid >> 4;
    const int lk = tid & 15, lm = tid >> 4;
    for (int k0 = 0; k0 < Kd; k0 += TK) {
        #pragma unroll
        for (int r = 0; r < 4; r++) {
            As[lk][lm + 16 * r] = A[(size_t)(m0 + lm + 16 * r) * lda + k0 + lk];
            Ws[lk][lm + 16 * r] = W[(size_t)(n0 + lm + 16 * r) * ldw + k0 + lk];
        }
        __syncthreads();
        #pragma unroll
        for (int kk = 0; kk < TK; kk++) {
            float4 a = *(const float4*)&As[kk][ty * 4];
            float4 b = *(const float4*)&Ws[kk][tx * 4];
            float av[4] = {a.x, a.y, a.z, a.w};
            float bv[4] = {b.x, b.y, b.z, b.w};
            #pragma unroll
            for (int i = 0; i < 4; i++)
                #pragma unroll
                for (int j = 0; j < 4; j++)
                    acc[i][j] += av[i] * bv[j];
        }
        __syncthreads();
    }
    if (EPI < 0) return; // (never; keeps template shape)
}

template<int EPI>
__global__ void gemm_tn_kernel(const float* __restrict__ A, int lda,
                               const float* __restrict__ W, int ldw,
                               const float* __restrict__ bias,
                               const float* __restrict__ res,
                               float* __restrict__ C, int ldc, int Kd) {
    int m0 = blockIdx.y * 64, n0 = blockIdx.x * 64;
    float acc[4][4] = {};
    gemm_tile_tn<EPI>(A, lda, W, ldw, bias, res, C, ldc, m0, n0, Kd, acc);
    const int tx = threadIdx.x & 15, ty = threadIdx.x >> 4;
    #pragma unroll
    for (int i = 0; i < 4; i++) {
        int m = m0 + ty * 4 + i;
        #pragma unroll
        for (int j = 0; j < 4; j++) {
            int n = n0 + tx * 4 + j;
            float v = acc[i][j];
            if (EPI >= 1) v += bias[n];
            if (EPI == 2) v += res[(size_t)m * ldc + n];
            if (EPI == 3) v = v / (1.0f + expf(-v));
            C[(size_t)m * ldc + n] = v;
        }
    }
}

// ---------------- batched pos GEMM: c2p / p2c ---------------------------------
// out[z, i, p] = sum_d A[b, i, h*64+d] * pos[p, h*64+d]   (z = b*H + h)
__global__ void gemm_pos_kernel(const float* __restrict__ qk,
                                const float* __restrict__ pos,
                                float* __restrict__ out) {
    int z = blockIdx.z; int b = z >> 3, h = z & 7;
    const float* A = qk + (size_t)b * Ssz * Dsz + h * DHsz;
    const float* W = pos + h * DHsz;
    float* C = out + (size_t)z * Ssz * NPOS;
    int m0 = blockIdx.y * 64;
    float acc[4][4] = {};
    gemm_tile_tn<0>(A, Dsz, W, Dsz, nullptr, nullptr, C, NPOS, m0, 0, DHsz, acc);
    const int tx = threadIdx.x & 15, ty = threadIdx.x >> 4;
    #pragma unroll
    for (int i = 0; i < 4; i++) {
        int m = m0 + ty * 4 + i;
        #pragma unroll
        for (int j = 0; j < 4; j++)
            C[(size_t)m * NPOS + tx * 4 + j] = acc[i][j];
    }
}

// ---------------- batched scores GEMM + disentangled bias ---------------------
__global__ void gemm_scores_kernel(const float* __restrict__ q,
                                   const float* __restrict__ k,
                                   const float* __restrict__ c2p,
                                   const float* __restrict__ p2c,
                                   const int* __restrict__ lut,
                                   float* __restrict__ scores) {
    int z = blockIdx.z; int b = z >> 3, h = z & 7;
    const float* A = q + (size_t)b * Ssz * Dsz + h * DHsz;
    const float* W = k + (size_t)b * Ssz * Dsz + h * DHsz;
    int m0 = blockIdx.y * 64, n0 = blockIdx.x * 64;
    float acc[4][4] = {};
    gemm_tile_tn<0>(A, Dsz, W, Dsz, nullptr, nullptr, nullptr, 0, m0, n0, DHsz, acc);
    const int tx = threadIdx.x & 15, ty = threadIdx.x >> 4;
    const float SCALE = 0.07216878364870323f;  // 1/sqrt(64*3)
    float* Crow = scores + (size_t)z * Ssz * Ssz;
    const float* c2pz = c2p + (size_t)z * Ssz * NPOS;
    const float* p2cz = p2c + (size_t)z * Ssz * NPOS;
    #pragma unroll
    for (int i = 0; i < 4; i++) {
        int m = m0 + ty * 4 + i;
        #pragma unroll
        for (int j = 0; j < 4; j++) {
            int n = n0 + tx * 4 + j;
            int idx = lut[m - n + (Ssz - 1)];
            float v = acc[i][j] + c2pz[(size_t)m * NPOS + idx] + p2cz[(size_t)n * NPOS + idx];
            Crow[(size_t)m * Ssz + n] = v * SCALE;
        }
    }
}

// ---------------- softmax over rows of 1024 -----------------------------------
__global__ void softmax_kernel(float* __restrict__ scores) {
    float* p = scores + (size_t)blockIdx.x * Ssz;
    int tid = threadIdx.x;  // 256
    __shared__ float red[8];
    float v[4];
    float mx = -3.4e38f;
    #pragma unroll
    for (int r = 0; r < 4; r++) { v[r] = p[tid + 256 * r]; mx = fmaxf(mx, v[r]); }
    #pragma unroll
    for (int o = 16; o; o >>= 1) mx = fmaxf(mx, __shfl_xor_sync(0xffffffffu, mx, o));
    if ((tid & 31) == 0) red[tid >> 5] = mx;
    __syncthreads();
    float m = red[0];
    #pragma unroll
    for (int i = 1; i < 8; i++) m = fmaxf(m, red[i]);
    float s = 0.f;
    #pragma unroll
    for (int r = 0; r < 4; r++) { v[r] = expf(v[r] - m); s += v[r]; }
    #pragma unroll
    for (int o = 16; o; o >>= 1) s += __shfl_xor_sync(0xffffffffu, s, o);
    __syncthreads();
    if ((tid & 31) == 0) red[tid >> 5] = s;
    __syncthreads();
    float tot = 0.f;
    #pragma unroll
    for (int i = 0; i < 8; i++) tot += red[i];
    float inv = 1.0f / tot;
    #pragma unroll
    for (int r = 0; r < 4; r++) p[tid + 256 * r] = v[r] * inv;
}

// ---------------- batched NN GEMM: ctx = probs @ V -----------------------------
// C[i, d] = sum_j A[i,j] * V[b, j, h*64+d];  writes into [B,S,D] head layout
__global__ void gemm_ctx_kernel(const float* __restrict__ probs,
                                const float* __restrict__ v,
                                float* __restrict__ ctx) {
    int z = blockIdx.z; int b = z >> 3, h = z & 7;
    const float* A  = probs + (size_t)z * Ssz * Ssz;           // lda = Ssz
    const float* Bm = v   + (size_t)b * Ssz * Dsz + h * DHsz;  // B[k][n], ldb = Dsz
    float* C        = ctx + (size_t)b * Ssz * Dsz + h * DHsz;  // ldc = Dsz
    int m0 = blockIdx.y * 64;
    __shared__ float As[TK][TPAD];
    __shared__ float Bs[TK][TPAD];
    const int tid = threadIdx.x;
    const int tx = tid & 15, ty = tid >> 4;
    float acc[4][4] = {};
    const int lk = tid & 15, lm = tid >> 4;
    const int ln = tid & 63, lkb = tid >> 6;
    for (int k0 = 0; k0 < Ssz; k0 += TK) {
        #pragma unroll
        for (int r = 0; r < 4; r++)
            As[lk][lm + 16 * r] = A[(size_t)(m0 + lm + 16 * r) * Ssz + k0 + lk];
        #pragma unroll
        for (int r = 0; r < 4; r++)
            Bs[lkb + 4 * r][ln] = Bm[(size_t)(k0 + lkb + 4 * r) * Dsz + ln];
        __syncthreads();
        #pragma unroll
        for (int kk = 0; kk < TK; kk++) {
            float4 a = *(const float4*)&As[kk][ty * 4];
            float4 bq = *(const float4*)&Bs[kk][tx * 4];
            float av[4] = {a.x, a.y, a.z, a.w};
            float bv[4] = {bq.x, bq.y, bq.z, bq.w};
            #pragma unroll
            for (int i = 0; i < 4; i++)
                #pragma unroll
                for (int j = 0; j < 4; j++)
                    acc[i][j] += av[i] * bv[j];
        }
        __syncthreads();
    }
    #pragma unroll
    for (int i = 0; i < 4; i++) {
        int m = m0 + ty * 4 + i;
        #pragma unroll
        for (int j = 0; j < 4; j++)
            C[(size_t)m * Dsz + tx * 4 + j] = acc[i][j];
    }
}

// =============================== launch ========================================
extern "C" void kernel_launch(void* const* d_in, const int* in_sizes, int n_in,
                              void* d_out, int out_size) {
    const float* x      = (const float*)d_in[0];
    const float* ln1g   = (const float*)d_in[1];
    const float* ln1b   = (const float*)d_in[2];
    const float* dww    = (const float*)d_in[3];
    const float* dwb    = (const float*)d_in[4];
    const float* pww    = (const float*)d_in[5];
    const float* pwb    = (const float*)d_in[6];
    const float* ln2g   = (const float*)d_in[7];
    const float* ln2b   = (const float*)d_in[8];
    const float* qw     = (const float*)d_in[9];
    const float* qb     = (const float*)d_in[10];
    const float* kw     = (const float*)d_in[11];
    const float* kb     = (const float*)d_in[12];
    const float* vw     = (const float*)d_in[13];
    const float* vb     = (const float*)d_in[14];
    const float* ow     = (const float*)d_in[15];
    const float* ob     = (const float*)d_in[16];
    const float* relemb = (const float*)d_in[17];
    const float* ln3g   = (const float*)d_in[18];
    const float* ln3b   = (const float*)d_in[19];
    const float* w1     = (const float*)d_in[20];
    const float* b1     = (const float*)d_in[21];
    const float* w2     = (const float*)d_in[22];
    const float* b2     = (const float*)d_in[23];
    float* out = (float*)d_out;

    float *xn, *conv, *x1, *x2, *q, *k, *v, *ctx, *posk, *posq, *c2p, *p2c, *scores, *ff;
    int* lut;
    cudaGetSymbolAddress((void**)&xn,     g_xn);
    cudaGetSymbolAddress((void**)&conv,   g_conv);
    cudaGetSymbolAddress((void**)&x1,     g_x1);
    cudaGetSymbolAddress((void**)&x2,     g_x2);
    cudaGetSymbolAddress((void**)&q,      g_q);
    cudaGetSymbolAddress((void**)&k,      g_k);
    cudaGetSymbolAddress((void**)&v,      g_v);
    cudaGetSymbolAddress((void**)&ctx,    g_ctx);
    cudaGetSymbolAddress((void**)&posk,   g_posk);
    cudaGetSymbolAddress((void**)&posq,   g_posq);
    cudaGetSymbolAddress((void**)&c2p,    g_c2p);
    cudaGetSymbolAddress((void**)&p2c,    g_p2c);
    cudaGetSymbolAddress((void**)&scores, g_scores);
    cudaGetSymbolAddress((void**)&ff,     g_ff);
    cudaGetSymbolAddress((void**)&lut,    g_lut);

    // LUT (cheap; rebuilt every call for determinism)
    build_lut_kernel<<<8, 256>>>(lut);

    // ---- conv block ----
    layernorm_kernel<<<NROWS, 256>>>(x, ln1g, ln1b, xn);
    dwconv_silu_kernel<<<(Bsz*Ssz*Dsz + 255) / 256, 256>>>(xn, dww, dwb, conv);
    gemm_tn_kernel<2><<<dim3(Dsz/64, NROWS/64), 256>>>(conv, Dsz, pww, Dsz, pwb, x, x1, Dsz, Dsz);

    // ---- attention block ----
    layernorm_kernel<<<NROWS, 256>>>(x1, ln2g, ln2b, xn);
    gemm_tn_kernel<1><<<dim3(Dsz/64, NROWS/64), 256>>>(xn, Dsz, qw, Dsz, qb, nullptr, q, Dsz, Dsz);
    gemm_tn_kernel<1><<<dim3(Dsz/64, NROWS/64), 256>>>(xn, Dsz, kw, Dsz, kb, nullptr, k, Dsz, Dsz);
    gemm_tn_kernel<1><<<dim3(Dsz/64, NROWS/64), 256>>>(xn, Dsz, vw, Dsz, vb, nullptr, v, Dsz, Dsz);
    // pos projections: [64, D] = rel_emb @ {k,q}_w^T + bias
    gemm_tn_kernel<1><<<dim3(Dsz/64, 1), 256>>>(relemb, Dsz, kw, Dsz, kb, nullptr, posk, Dsz, Dsz);
    gemm_tn_kernel<1><<<dim3(Dsz/64, 1), 256>>>(relemb, Dsz, qw, Dsz, qb, nullptr, posq, Dsz, Dsz);
    // c2p[z,i,p] = q_i . posk_p ; p2c[z,j,p] = k_j . posq_p
    gemm_pos_kernel<<<dim3(1, Ssz/64, Bsz*Hsz), 256>>>(q, posk, c2p);
    gemm_pos_kernel<<<dim3(1, Ssz/64, Bsz*Hsz), 256>>>(k, posq, p2c);
    // scores + disentangled bias
    gemm_scores_kernel<<<dim3(Ssz/64, Ssz/64, Bsz*Hsz), 256>>>(q, k, c2p, p2c, lut, scores);
    softmax_kernel<<<Bsz*Hsz*Ssz, 256>>>(scores);
    gemm_ctx_kernel<<<dim3(1, Ssz/64, Bsz*Hsz), 256>>>(scores, v, ctx);
    gemm_tn_kernel<2><<<dim3(Dsz/64, NROWS/64), 256>>>(ctx, Dsz, ow, Dsz, ob, x1, x2, Dsz, Dsz);

    // ---- FFN block ----
    layernorm_kernel<<<NROWS, 256>>>(x2, ln3g, ln3b, xn);
    gemm_tn_kernel<3><<<dim3(FFsz/64, NROWS/64), 256>>>(xn, Dsz, w1, Dsz, b1, nullptr, ff, FFsz, Dsz);
    gemm_tn_kernel<2><<<dim3(Dsz/64, NROWS/64), 256>>>(ff, FFsz, w2, FFsz, b2, x2, out, Dsz, FFsz);
}

// round 2
// speedup vs baseline: 2.2383x; 2.2383x over previous
#include <cuda_runtime.h>
#include <math.h>
#include <stdint.h>

#define Bsz 8
#define Ssz 1024
#define Dsz 512
#define Hsz 8
#define DHsz 64
#define FFsz 1024
#define NPOS 64          // 2*SPAN
#define NROWS (Bsz*Ssz)  // 8192

// ---------------- scratch (device globals; no allocation allowed) ------------
__device__ float g_xn  [Bsz*Ssz*Dsz];
__device__ float g_conv[Bsz*Ssz*Dsz];
__device__ float g_x1  [Bsz*Ssz*Dsz];
__device__ float g_x2  [Bsz*Ssz*Dsz];
__device__ float g_q   [Bsz*Ssz*Dsz];
__device__ float g_k   [Bsz*Ssz*Dsz];
__device__ float g_v   [Bsz*Ssz*Dsz];
__device__ float g_vt  [Bsz*Ssz*Dsz];   // [B, D, S]
__device__ float g_ctx [Bsz*Ssz*Dsz];
__device__ float g_posk[NPOS*Dsz];
__device__ float g_posq[NPOS*Dsz];
__device__ float g_c2p [Bsz*Hsz*Ssz*NPOS];
__device__ float g_p2c [Bsz*Hsz*Ssz*NPOS];
__device__ float g_scores[(size_t)Bsz*Hsz*Ssz*Ssz];  // 256 MB
__device__ float g_ff  [Bsz*Ssz*FFsz];
__device__ int   g_lut [2*Ssz];

// ---------------- relative-position bucket LUT --------------------------------
__global__ void build_lut_kernel(int* __restrict__ lut) {
    int t = blockIdx.x * blockDim.x + threadIdx.x;
    if (t >= 2*Ssz - 1) return;
    int rel = t - (Ssz - 1);   // i - j
    const int mid = 16;        // BUCKETS/2
    int bucket;
    if (rel > -mid && rel < mid) {
        bucket = rel;
    } else {
        float absp = fabsf((float)rel);
        if (absp <= (float)mid) {
            bucket = rel;
        } else {
            float logp = ceilf(logf(absp / 16.0f) / logf(127.0f / 16.0f) * 15.0f) + 16.0f;
            bucket = (rel > 0 ? 1 : -1) * (int)logp;
        }
    }
    int idx = bucket + 32;
    idx = min(max(idx, 0), 63);
    lut[t] = idx;
}

// ---------------- LayerNorm (D=512, one block per row) ------------------------
__global__ void layernorm_kernel(const float* __restrict__ x,
                                 const float* __restrict__ g,
                                 const float* __restrict__ bb,
                                 float* __restrict__ out) {
    const float* xr = x + (size_t)blockIdx.x * Dsz;
    float* orow = out + (size_t)blockIdx.x * Dsz;
    int tid = threadIdx.x;  // 256
    float v0 = xr[tid], v1 = xr[tid + 256];
    float s = v0 + v1, ss = v0 * v0 + v1 * v1;
    __shared__ float r1[8], r2[8];
    #pragma unroll
    for (int o = 16; o; o >>= 1) {
        s  += __shfl_xor_sync(0xffffffffu, s, o);
        ss += __shfl_xor_sync(0xffffffffu, ss, o);
    }
    if ((tid & 31) == 0) { r1[tid >> 5] = s; r2[tid >> 5] = ss; }
    __syncthreads();
    float S1 = 0.f, S2 = 0.f;
    #pragma unroll
    for (int i = 0; i < 8; i++) { S1 += r1[i]; S2 += r2[i]; }
    float mean = S1 * (1.0f / Dsz);
    float var  = S2 * (1.0f / Dsz) - mean * mean;
    float rs = rsqrtf(var + 1e-5f);
    orow[tid]       = (v0 - mean) * rs * g[tid]       + bb[tid];
    orow[tid + 256] = (v1 - mean) * rs * g[tid + 256] + bb[tid + 256];
}

// ---------------- depthwise conv (K=3 along S) + bias + SiLU ------------------
__global__ void dwconv_silu_kernel(const float* __restrict__ xn,
                                   const float* __restrict__ w,
                                   const float* __restrict__ bias,
                                   float* __restrict__ out) {
    size_t idx = (size_t)blockIdx.x * blockDim.x + threadIdx.x;
    if (idx >= (size_t)Bsz * Ssz * Dsz) return;
    int d = (int)(idx % Dsz);
    int s = (int)((idx / Dsz) % Ssz);
    const float* base = xn + idx;
    float w0 = w[d * 3 + 0], w1 = w[d * 3 + 1], w2 = w[d * 3 + 2];
    float acc = bias[d] + base[0] * w1;
    if (s > 0)        acc += base[-Dsz] * w0;
    if (s < Ssz - 1)  acc += base[ Dsz] * w2;
    out[idx] = acc / (1.0f + expf(-acc));  // silu
}

// ---------------- V transpose: [B,S,D] -> [B,D,S] ------------------------------
__global__ void transpose_v_kernel(const float* __restrict__ v, float* __restrict__ vt) {
    __shared__ float tile[32][33];
    int b = blockIdx.z;
    int s0 = blockIdx.x * 32, d0 = blockIdx.y * 32;
    int tx = threadIdx.x, ty = threadIdx.y;  // 32 x 8
    #pragma unroll
    for (int j = 0; j < 32; j += 8)
        tile[ty + j][tx] = v[((size_t)b * Ssz + s0 + ty + j) * Dsz + d0 + tx];
    __syncthreads();
    #pragma unroll
    for (int j = 0; j < 32; j += 8)
        vt[((size_t)b * Dsz + d0 + ty + j) * Ssz + s0 + tx] = tile[tx][ty + j];
}

// ---------------- mma.tf32 helpers ---------------------------------------------
__device__ __forceinline__ void mma_tf32(float c[4], const uint32_t a[4], const uint32_t b[2]) {
    asm volatile(
        "mma.sync.aligned.m16n8k8.row.col.f32.tf32.tf32.f32 "
        "{%0,%1,%2,%3}, {%4,%5,%6,%7}, {%8,%9}, {%0,%1,%2,%3};"
        : "+f"(c[0]), "+f"(c[1]), "+f"(c[2]), "+f"(c[3])
        : "r"(a[0]), "r"(a[1]), "r"(a[2]), "r"(a[3]), "r"(b[0]), "r"(b[1]));
}

#define CP_ASYNC16(dst_u32, src_ptr) \
    asm volatile("cp.async.ca.shared.global [%0], [%1], 16;" :: "r"(dst_u32), "l"(src_ptr))
#define CP_COMMIT() asm volatile("cp.async.commit_group;")
#define CP_WAIT1()  asm volatile("cp.async.wait_group 1;")
#define CP_WAIT0()  asm volatile("cp.async.wait_group 0;")

// ---------------- tensor-core TN GEMM -------------------------------------------
// C[m,n] = sum_k A[m,k] * W[n,k]   (both row-major over their [rows, K])
// CTA tile: 128 x CN.  8 warps.  KT=16, double-buffered cp.async.
// smem row stride 20 floats -> conflict-free fragment LDS.
// EPI: 0 none, 1 +bias, 2 +bias+res, 3 silu(+bias), 4 scores epilogue
// MODE: 0 plain, 1 scores (batched q/k + disentangled bias),
//       2 ctx (probs @ vt), 3 pos (q/k vs pos table)
#define SSTRIDE 20

template<int CN, int EPI, int MODE>
__global__ void __launch_bounds__(256, 2) gemm_mma_kernel(
    const float* __restrict__ A0, int lda,
    const float* __restrict__ W0, int ldw,
    const float* __restrict__ bias, const float* __restrict__ res,
    float* __restrict__ C0, int ldc, int K,
    const float* __restrict__ c2p, const float* __restrict__ p2c,
    const int* __restrict__ lut)
{
    constexpr int NWN = CN / 32;     // warps along N
    constexpr int NWM = 8 / NWN;     // warps along M
    constexpr int MT  = 8 / NWM;     // m16 tiles per warp (4 or 2)

    __shared__ float As[2][128 * SSTRIDE];
    __shared__ float Ws[2][CN  * SSTRIDE];

    const int tid  = threadIdx.x;
    const int wid  = tid >> 5, lane = tid & 31;
    const int g    = lane >> 2, tg = lane & 3;
    const int wm   = wid % NWM, wn = wid / NWM;

    const int z = blockIdx.z, bb = z >> 3, hh = z & 7;
    const float* A = A0; const float* W = W0; float* C = C0;
    const float* c2pz = c2p; const float* p2cz = p2c;
    if (MODE == 1) {
        size_t off = (size_t)bb * Ssz * Dsz + hh * DHsz;
        A = A0 + off; W = W0 + off;
        C = C0 + (size_t)z * Ssz * Ssz;
        c2pz = c2p + (size_t)z * Ssz * NPOS;
        p2cz = p2c + (size_t)z * Ssz * NPOS;
    } else if (MODE == 2) {
        A = A0 + (size_t)z * Ssz * Ssz;
        W = W0 + (size_t)bb * Dsz * Ssz + (size_t)hh * DHsz * Ssz;
        C = C0 + (size_t)bb * Ssz * Dsz + hh * DHsz;
    } else if (MODE == 3) {
        A = A0 + (size_t)bb * Ssz * Dsz + hh * DHsz;
        W = W0 + hh * DHsz;
        C = C0 + (size_t)z * Ssz * NPOS;
    }

    const int m_cta = blockIdx.y * 128, n_cta = blockIdx.x * CN;

    const uint32_t sA = (uint32_t)__cvta_generic_to_shared(&As[0][0]);
    const uint32_t sW = (uint32_t)__cvta_generic_to_shared(&Ws[0][0]);

    const int qd = (tid & 3) * 4;   // float col within 16-wide tile
    const int rr = tid >> 2;        // 0..63

    // async fetch of K-tile `t` into buffer `buf`
    auto fetch = [&](int t, int buf) {
        int k0 = t * 16;
        #pragma unroll
        for (int r = 0; r < 2; r++) {
            int row = rr + 64 * r;
            uint32_t d = sA + (uint32_t)(buf * 128 * SSTRIDE + row * SSTRIDE + qd) * 4u;
            CP_ASYNC16(d, A + (size_t)(m_cta + row) * lda + k0 + qd);
        }
        #pragma unroll
        for (int r = 0; r < CN / 64; r++) {
            int row = rr + 64 * r;
            uint32_t d = sW + (uint32_t)(buf * CN * SSTRIDE + row * SSTRIDE + qd) * 4u;
            CP_ASYNC16(d, W + (size_t)(n_cta + row) * ldw + k0 + qd);
        }
        CP_COMMIT();
    };

    float acc[MT][4][4] = {};

    const int T = K / 16;
    fetch(0, 0);
    for (int it = 0; it < T; it++) {
        if (it + 1 < T) { fetch(it + 1, (it + 1) & 1); CP_WAIT1(); }
        else            { CP_WAIT0(); }
        __syncthreads();
        const float* Ab = &As[it & 1][0];
        const float* Wb = &Ws[it & 1][0];
        #pragma unroll
        for (int ks = 0; ks < 2; ks++) {
            const int kk = ks * 8;
            uint32_t af[MT][4];
            #pragma unroll
            for (int im = 0; im < MT; im++) {
                const uint32_t* p = (const uint32_t*)&Ab[(wm * MT * 16 + im * 16 + g) * SSTRIDE + kk + tg];
                af[im][0] = p[0];
                af[im][1] = p[8 * SSTRIDE];
                af[im][2] = p[4];
                af[im][3] = p[8 * SSTRIDE + 4];
            }
            uint32_t bf[4][2];
            #pragma unroll
            for (int in = 0; in < 4; in++) {
                const uint32_t* p = (const uint32_t*)&Wb[(wn * 32 + in * 8 + g) * SSTRIDE + kk + tg];
                bf[in][0] = p[0];
                bf[in][1] = p[4];
            }
            #pragma unroll
            for (int im = 0; im < MT; im++)
                #pragma unroll
                for (int in = 0; in < 4; in++)
                    mma_tf32(acc[im][in], af[im], bf[in]);
        }
        __syncthreads();
    }

    // epilogue
    const float SCALE = 0.07216878364870323f;  // 1/sqrt(64*3)
    #pragma unroll
    for (int im = 0; im < MT; im++) {
        int mrow0 = m_cta + wm * MT * 16 + im * 16 + g;
        #pragma unroll
        for (int in = 0; in < 4; in++) {
            int ncol0 = n_cta + wn * 32 + in * 8 + tg * 2;
            #pragma unroll
            for (int e = 0; e < 4; e++) {
                int m = mrow0 + ((e >= 2) ? 8 : 0);
                int n = ncol0 + (e & 1);
                float vv = acc[im][in][e];
                if (EPI == 1 || EPI == 2 || EPI == 3) vv += bias[n];
                if (EPI == 2) vv += res[(size_t)m * ldc + n];
                if (EPI == 3) vv = vv / (1.0f + expf(-vv));
                if (EPI == 4) {
                    int idx = lut[m - n + (Ssz - 1)];
                    vv = (vv + c2pz[(size_t)m * NPOS + idx]
                             + p2cz[(size_t)n * NPOS + idx]) * SCALE;
                }
                C[(size_t)m * ldc + n] = vv;
            }
        }
    }
}

// ---------------- small SIMT GEMM (pos projections, M=64) ---------------------
#define TK 16
#define TPAD 68
__global__ void gemm_tn_small_kernel(const float* __restrict__ A, int lda,
                                     const float* __restrict__ W, int ldw,
                                     const float* __restrict__ bias,
                                     float* __restrict__ C, int ldc, int Kd) {
    int m0 = blockIdx.y * 64, n0 = blockIdx.x * 64;
    __shared__ float As[TK][TPAD];
    __shared__ float Ws2[TK][TPAD];
    const int tid = threadIdx.x;
    const int tx = tid & 15, ty = tid >> 4;
    const int lk = tid & 15, lm = tid >> 4;
    float acc[4][4] = {};
    for (int k0 = 0; k0 < Kd; k0 += TK) {
        #pragma unroll
        for (int r = 0; r < 4; r++) {
            As[lk][lm + 16 * r]  = A[(size_t)(m0 + lm + 16 * r) * lda + k0 + lk];
            Ws2[lk][lm + 16 * r] = W[(size_t)(n0 + lm + 16 * r) * ldw + k0 + lk];
        }
        __syncthreads();
        #pragma unroll
        for (int kk = 0; kk < TK; kk++) {
            float4 a = *(const float4*)&As[kk][ty * 4];
            float4 b = *(const float4*)&Ws2[kk][tx * 4];
            float av[4] = {a.x, a.y, a.z, a.w};
            float bv[4] = {b.x, b.y, b.z, b.w};
            #pragma unroll
            for (int i = 0; i < 4; i++)
                #pragma unroll
                for (int j = 0; j < 4; j++)
                    acc[i][j] += av[i] * bv[j];
        }
        __syncthreads();
    }
    #pragma unroll
    for (int i = 0; i < 4; i++) {
        int m = m0 + ty * 4 + i;
        #pragma unroll
        for (int j = 0; j < 4; j++) {
            int n = n0 + tx * 4 + j;
            C[(size_t)m * ldc + n] = acc[i][j] + bias[n];
        }
    }
}

// ---------------- softmax over rows of 1024 -----------------------------------
__global__ void softmax_kernel(float* __restrict__ scores) {
    float4* p = (float4*)(scores + (size_t)blockIdx.x * Ssz);
    int tid = threadIdx.x;  // 256
    __shared__ float red[8];
    float4 v = p[tid];
    float mx = fmaxf(fmaxf(v.x, v.y), fmaxf(v.z, v.w));
    #pragma unroll
    for (int o = 16; o; o >>= 1) mx = fmaxf(mx, __shfl_xor_sync(0xffffffffu, mx, o));
    if ((tid & 31) == 0) red[tid >> 5] = mx;
    __syncthreads();
    float m = red[0];
    #pragma unroll
    for (int i = 1; i < 8; i++) m = fmaxf(m, red[i]);
    v.x = expf(v.x - m); v.y = expf(v.y - m); v.z = expf(v.z - m); v.w = expf(v.w - m);
    float s = v.x + v.y + v.z + v.w;
    #pragma unroll
    for (int o = 16; o; o >>= 1) s += __shfl_xor_sync(0xffffffffu, s, o);
    __syncthreads();
    if ((tid & 31) == 0) red[tid >> 5] = s;
    __syncthreads();
    float tot = 0.f;
    #pragma unroll
    for (int i = 0; i < 8; i++) tot += red[i];
    float inv = 1.0f / tot;
    v.x *= inv; v.y *= inv; v.z *= inv; v.w *= inv;
    p[tid] = v;
}

// =============================== launch ========================================
extern "C" void kernel_launch(void* const* d_in, const int* in_sizes, int n_in,
                              void* d_out, int out_size) {
    const float* x      = (const float*)d_in[0];
    const float* ln1g   = (const float*)d_in[1];
    const float* ln1b   = (const float*)d_in[2];
    const float* dww    = (const float*)d_in[3];
    const float* dwb    = (const float*)d_in[4];
    const float* pww    = (const float*)d_in[5];
    const float* pwb    = (const float*)d_in[6];
    const float* ln2g   = (const float*)d_in[7];
    const float* ln2b   = (const float*)d_in[8];
    const float* qw     = (const float*)d_in[9];
    const float* qb     = (const float*)d_in[10];
    const float* kw     = (const float*)d_in[11];
    const float* kb     = (const float*)d_in[12];
    const float* vw     = (const float*)d_in[13];
    const float* vb     = (const float*)d_in[14];
    const float* ow     = (const float*)d_in[15];
    const float* ob     = (const float*)d_in[16];
    const float* relemb = (const float*)d_in[17];
    const float* ln3g   = (const float*)d_in[18];
    const float* ln3b   = (const float*)d_in[19];
    const float* w1     = (const float*)d_in[20];
    const float* b1     = (const float*)d_in[21];
    const float* w2     = (const float*)d_in[22];
    const float* b2     = (const float*)d_in[23];
    float* out = (float*)d_out;

    float *xn, *conv, *x1, *x2, *q, *k, *v, *vt, *ctx, *posk, *posq, *c2p, *p2c, *scores, *ff;
    int* lut;
    cudaGetSymbolAddress((void**)&xn,     g_xn);
    cudaGetSymbolAddress((void**)&conv,   g_conv);
    cudaGetSymbolAddress((void**)&x1,     g_x1);
    cudaGetSymbolAddress((void**)&x2,     g_x2);
    cudaGetSymbolAddress((void**)&q,      g_q);
    cudaGetSymbolAddress((void**)&k,      g_k);
    cudaGetSymbolAddress((void**)&v,      g_v);
    cudaGetSymbolAddress((void**)&vt,     g_vt);
    cudaGetSymbolAddress((void**)&ctx,    g_ctx);
    cudaGetSymbolAddress((void**)&posk,   g_posk);
    cudaGetSymbolAddress((void**)&posq,   g_posq);
    cudaGetSymbolAddress((void**)&c2p,    g_c2p);
    cudaGetSymbolAddress((void**)&p2c,    g_p2c);
    cudaGetSymbolAddress((void**)&scores, g_scores);
    cudaGetSymbolAddress((void**)&ff,     g_ff);
    cudaGetSymbolAddress((void**)&lut,    g_lut);

    build_lut_kernel<<<8, 256>>>(lut);

    // ---- conv block ----
    layernorm_kernel<<<NROWS, 256>>>(x, ln1g, ln1b, xn);
    dwconv_silu_kernel<<<(Bsz*Ssz*Dsz + 255) / 256, 256>>>(xn, dww, dwb, conv);
    gemm_mma_kernel<128,2,0><<<dim3(Dsz/128, NROWS/128, 1), 256>>>(
        conv, Dsz, pww, Dsz, pwb, x, x1, Dsz, Dsz, nullptr, nullptr, nullptr);

    // ---- attention block ----
    layernorm_kernel<<<NROWS, 256>>>(x1, ln2g, ln2b, xn);
    gemm_mma_kernel<128,1,0><<<dim3(Dsz/128, NROWS/128, 1), 256>>>(
        xn, Dsz, qw, Dsz, qb, nullptr, q, Dsz, Dsz, nullptr, nullptr, nullptr);
    gemm_mma_kernel<128,1,0><<<dim3(Dsz/128, NROWS/128, 1), 256>>>(
        xn, Dsz, kw, Dsz, kb, nullptr, k, Dsz, Dsz, nullptr, nullptr, nullptr);
    gemm_mma_kernel<128,1,0><<<dim3(Dsz/128, NROWS/128, 1), 256>>>(
        xn, Dsz, vw, Dsz, vb, nullptr, v, Dsz, Dsz, nullptr, nullptr, nullptr);
    transpose_v_kernel<<<dim3(Ssz/32, Dsz/32, Bsz), dim3(32, 8)>>>(v, vt);

    // pos projections: [64, D] = rel_emb @ {k,q}_w^T + bias  (SIMT, tiny)
    gemm_tn_small_kernel<<<dim3(Dsz/64, 1), 256>>>(relemb, Dsz, kw, Dsz, kb, posk, Dsz, Dsz);
    gemm_tn_small_kernel<<<dim3(Dsz/64, 1), 256>>>(relemb, Dsz, qw, Dsz, qb, posq, Dsz, Dsz);

    // c2p[z,i,p] = q_i . posk_p ; p2c[z,j,p] = k_j . posq_p
    gemm_mma_kernel<64,0,3><<<dim3(1, Ssz/128, Bsz*Hsz), 256>>>(
        q, Dsz, posk, Dsz, nullptr, nullptr, c2p, NPOS, DHsz, nullptr, nullptr, nullptr);
    gemm_mma_kernel<64,0,3><<<dim3(1, Ssz/128, Bsz*Hsz), 256>>>(
        k, Dsz, posq, Dsz, nullptr, nullptr, p2c, NPOS, DHsz, nullptr, nullptr, nullptr);

    // scores + disentangled bias
    gemm_mma_kernel<128,4,1><<<dim3(Ssz/128, Ssz/128, Bsz*Hsz), 256>>>(
        q, Dsz, k, Dsz, nullptr, nullptr, scores, Ssz, DHsz, c2p, p2c, lut);
    softmax_kernel<<<Bsz*Hsz*Ssz, 256>>>(scores);

    // ctx = probs @ V   (V pre-transposed to [B,D,S])
    gemm_mma_kernel<64,0,2><<<dim3(1, Ssz/128, Bsz*Hsz), 256>>>(
        scores, Ssz, vt, Ssz, nullptr, nullptr, ctx, Dsz, Ssz, nullptr, nullptr, nullptr);
    gemm_mma_kernel<128,2,0><<<dim3(Dsz/128, NROWS/128, 1), 256>>>(
        ctx, Dsz, ow, Dsz, ob, x1, x2, Dsz, Dsz, nullptr, nullptr, nullptr);

    // ---- FFN block ----
    layernorm_kernel<<<NROWS, 256>>>(x2, ln3g, ln3b, xn);
    gemm_mma_kernel<128,3,0><<<dim3(FFsz/128, NROWS/128, 1), 256>>>(
        xn, Dsz, w1, Dsz, b1, nullptr, ff, FFsz, Dsz, nullptr, nullptr, nullptr);
    gemm_mma_kernel<128,2,0><<<dim3(Dsz/128, NROWS/128, 1), 256>>>(
        ff, FFsz, w2, FFsz, b2, x2, out, Dsz, FFsz, nullptr, nullptr, nullptr);
}

// round 3
// speedup vs baseline: 2.4585x; 1.0984x over previous
#include <cuda_runtime.h>
#include <math.h>
#include <stdint.h>

#define Bsz 8
#define Ssz 1024
#define Dsz 512
#define Hsz 8
#define DHsz 64
#define FFsz 1024
#define NPOS 64          // 2*SPAN
#define NROWS (Bsz*Ssz)  // 8192

// ---------------- scratch (device globals; no allocation allowed) ------------
__device__ float g_xn  [Bsz*Ssz*Dsz];
__device__ float g_conv[Bsz*Ssz*Dsz];
__device__ float g_x1  [Bsz*Ssz*Dsz];
__device__ float g_x2  [Bsz*Ssz*Dsz];
__device__ float g_q   [Bsz*Ssz*Dsz];
__device__ float g_k   [Bsz*Ssz*Dsz];
__device__ float g_v   [Bsz*Ssz*Dsz];
__device__ float g_vt  [Bsz*Ssz*Dsz];   // [B, D, S]
__device__ float g_ctx [Bsz*Ssz*Dsz];
__device__ float g_posk[NPOS*Dsz];
__device__ float g_posq[NPOS*Dsz];
__device__ float g_c2p [Bsz*Hsz*Ssz*NPOS];
__device__ float g_p2c [Bsz*Hsz*Ssz*NPOS];
__device__ float g_ff  [Bsz*Ssz*FFsz];
__device__ int   g_lut [2*Ssz];

// ---------------- relative-position bucket LUT --------------------------------
__global__ void build_lut_kernel(int* __restrict__ lut) {
    int t = blockIdx.x * blockDim.x + threadIdx.x;
    if (t >= 2*Ssz - 1) return;
    int rel = t - (Ssz - 1);   // i - j
    const int mid = 16;        // BUCKETS/2
    int bucket;
    if (rel > -mid && rel < mid) {
        bucket = rel;
    } else {
        float absp = fabsf((float)rel);
        if (absp <= (float)mid) {
            bucket = rel;
        } else {
            float logp = ceilf(logf(absp / 16.0f) / logf(127.0f / 16.0f) * 15.0f) + 16.0f;
            bucket = (rel > 0 ? 1 : -1) * (int)logp;
        }
    }
    int idx = bucket + 32;
    idx = min(max(idx, 0), 63);
    lut[t] = idx;
}

// ---------------- LayerNorm (D=512, one block per row) ------------------------
__global__ void layernorm_kernel(const float* __restrict__ x,
                                 const float* __restrict__ g,
                                 const float* __restrict__ bb,
                                 float* __restrict__ out) {
    const float* xr = x + (size_t)blockIdx.x * Dsz;
    float* orow = out + (size_t)blockIdx.x * Dsz;
    int tid = threadIdx.x;  // 256
    float v0 = xr[tid], v1 = xr[tid + 256];
    float s = v0 + v1, ss = v0 * v0 + v1 * v1;
    __shared__ float r1[8], r2[8];
    #pragma unroll
    for (int o = 16; o; o >>= 1) {
        s  += __shfl_xor_sync(0xffffffffu, s, o);
        ss += __shfl_xor_sync(0xffffffffu, ss, o);
    }
    if ((tid & 31) == 0) { r1[tid >> 5] = s; r2[tid >> 5] = ss; }
    __syncthreads();
    float S1 = 0.f, S2 = 0.f;
    #pragma unroll
    for (int i = 0; i < 8; i++) { S1 += r1[i]; S2 += r2[i]; }
    float mean = S1 * (1.0f / Dsz);
    float var  = S2 * (1.0f / Dsz) - mean * mean;
    float rs = rsqrtf(var + 1e-5f);
    orow[tid]       = (v0 - mean) * rs * g[tid]       + bb[tid];
    orow[tid + 256] = (v1 - mean) * rs * g[tid + 256] + bb[tid + 256];
}

// ---------------- depthwise conv (K=3 along S) + bias + SiLU ------------------
__global__ void dwconv_silu_kernel(const float* __restrict__ xn,
                                   const float* __restrict__ w,
                                   const float* __restrict__ bias,
                                   float* __restrict__ out) {
    size_t idx = (size_t)blockIdx.x * blockDim.x + threadIdx.x;
    if (idx >= (size_t)Bsz * Ssz * Dsz) return;
    int d = (int)(idx % Dsz);
    int s = (int)((idx / Dsz) % Ssz);
    const float* base = xn + idx;
    float w0 = w[d * 3 + 0], w1 = w[d * 3 + 1], w2 = w[d * 3 + 2];
    float acc = bias[d] + base[0] * w1;
    if (s > 0)        acc += base[-Dsz] * w0;
    if (s < Ssz - 1)  acc += base[ Dsz] * w2;
    out[idx] = acc / (1.0f + expf(-acc));  // silu
}

// ---------------- V transpose: [B,S,D] -> [B,D,S] ------------------------------
__global__ void transpose_v_kernel(const float* __restrict__ v, float* __restrict__ vt) {
    __shared__ float tile[32][33];
    int b = blockIdx.z;
    int s0 = blockIdx.x * 32, d0 = blockIdx.y * 32;
    int tx = threadIdx.x, ty = threadIdx.y;  // 32 x 8
    #pragma unroll
    for (int j = 0; j < 32; j += 8)
        tile[ty + j][tx] = v[((size_t)b * Ssz + s0 + ty + j) * Dsz + d0 + tx];
    __syncthreads();
    #pragma unroll
    for (int j = 0; j < 32; j += 8)
        vt[((size_t)b * Dsz + d0 + ty + j) * Ssz + s0 + tx] = tile[tx][ty + j];
}

// ---------------- mma.tf32 helpers ---------------------------------------------
__device__ __forceinline__ void mma_tf32(float c[4], const uint32_t a[4], const uint32_t b[2]) {
    asm volatile(
        "mma.sync.aligned.m16n8k8.row.col.f32.tf32.tf32.f32 "
        "{%0,%1,%2,%3}, {%4,%5,%6,%7}, {%8,%9}, {%0,%1,%2,%3};"
        : "+f"(c[0]), "+f"(c[1]), "+f"(c[2]), "+f"(c[3])
        : "r"(a[0]), "r"(a[1]), "r"(a[2]), "r"(a[3]), "r"(b[0]), "r"(b[1]));
}

#define CP_ASYNC16(dst_u32, src_ptr) \
    asm volatile("cp.async.ca.shared.global [%0], [%1], 16;" :: "r"(dst_u32), "l"(src_ptr))
#define CP_COMMIT() asm volatile("cp.async.commit_group;")
#define CP_WAIT2()  asm volatile("cp.async.wait_group 2;")
#define CP_WAIT1()  asm volatile("cp.async.wait_group 1;")
#define CP_WAIT0()  asm volatile("cp.async.wait_group 0;")

// ---------------- tensor-core TN GEMM -------------------------------------------
// C[m,n] = sum_k A[m,k] * W[n,k]
// EPI: 0 none, 1 +bias, 2 +bias+res, 3 silu(+bias)
// MODE: 0 plain, 3 pos (q/k vs pos table, batched over z)
#define SSTRIDE 20

template<int CN, int EPI, int MODE>
__global__ void __launch_bounds__(256, 2) gemm_mma_kernel(
    const float* __restrict__ A0, int lda,
    const float* __restrict__ W0, int ldw,
    const float* __restrict__ bias, const float* __restrict__ res,
    float* __restrict__ C0, int ldc, int K)
{
    constexpr int NWN = CN / 32;     // warps along N
    constexpr int NWM = 8 / NWN;     // warps along M
    constexpr int MT  = 8 / NWM;     // m16 tiles per warp

    __shared__ float As[2][128 * SSTRIDE];
    __shared__ float Ws[2][CN  * SSTRIDE];

    const int tid  = threadIdx.x;
    const int wid  = tid >> 5, lane = tid & 31;
    const int g    = lane >> 2, tg = lane & 3;
    const int wm   = wid % NWM, wn = wid / NWM;

    const int z = blockIdx.z, bb = z >> 3, hh = z & 7;
    const float* A = A0; const float* W = W0; float* C = C0;
    if (MODE == 3) {
        A = A0 + (size_t)bb * Ssz * Dsz + hh * DHsz;
        W = W0 + hh * DHsz;
        C = C0 + (size_t)z * Ssz * NPOS;
    }

    const int m_cta = blockIdx.y * 128, n_cta = blockIdx.x * CN;

    const uint32_t sA = (uint32_t)__cvta_generic_to_shared(&As[0][0]);
    const uint32_t sW = (uint32_t)__cvta_generic_to_shared(&Ws[0][0]);

    const int qd = (tid & 3) * 4;
    const int rr = tid >> 2;

    auto fetch = [&](int t, int buf) {
        int k0 = t * 16;
        #pragma unroll
        for (int r = 0; r < 2; r++) {
            int row = rr + 64 * r;
            uint32_t d = sA + (uint32_t)(buf * 128 * SSTRIDE + row * SSTRIDE + qd) * 4u;
            CP_ASYNC16(d, A + (size_t)(m_cta + row) * lda + k0 + qd);
        }
        #pragma unroll
        for (int r = 0; r < CN / 64; r++) {
            int row = rr + 64 * r;
            uint32_t d = sW + (uint32_t)(buf * CN * SSTRIDE + row * SSTRIDE + qd) * 4u;
            CP_ASYNC16(d, W + (size_t)(n_cta + row) * ldw + k0 + qd);
        }
        CP_COMMIT();
    };

    float acc[MT][4][4] = {};

    const int T = K / 16;
    fetch(0, 0);
    for (int it = 0; it < T; it++) {
        if (it + 1 < T) { fetch(it + 1, (it + 1) & 1); CP_WAIT1(); }
        else            { CP_WAIT0(); }
        __syncthreads();
        const float* Ab = &As[it & 1][0];
        const float* Wb = &Ws[it & 1][0];
        #pragma unroll
        for (int ks = 0; ks < 2; ks++) {
            const int kk = ks * 8;
            uint32_t af[MT][4];
            #pragma unroll
            for (int im = 0; im < MT; im++) {
                const uint32_t* p = (const uint32_t*)&Ab[(wm * MT * 16 + im * 16 + g) * SSTRIDE + kk + tg];
                af[im][0] = p[0];
                af[im][1] = p[8 * SSTRIDE];
                af[im][2] = p[4];
                af[im][3] = p[8 * SSTRIDE + 4];
            }
            uint32_t bf[4][2];
            #pragma unroll
            for (int in = 0; in < 4; in++) {
                const uint32_t* p = (const uint32_t*)&Wb[(wn * 32 + in * 8 + g) * SSTRIDE + kk + tg];
                bf[in][0] = p[0];
                bf[in][1] = p[4];
            }
            #pragma unroll
            for (int im = 0; im < MT; im++)
                #pragma unroll
                for (int in = 0; in < 4; in++)
                    mma_tf32(acc[im][in], af[im], bf[in]);
        }
        __syncthreads();
    }

    #pragma unroll
    for (int im = 0; im < MT; im++) {
        int mrow0 = m_cta + wm * MT * 16 + im * 16 + g;
        #pragma unroll
        for (int in = 0; in < 4; in++) {
            int ncol0 = n_cta + wn * 32 + in * 8 + tg * 2;
            #pragma unroll
            for (int e = 0; e < 4; e++) {
                int m = mrow0 + ((e >= 2) ? 8 : 0);
                int n = ncol0 + (e & 1);
                float vv = acc[im][in][e];
                if (EPI == 1 || EPI == 2 || EPI == 3) vv += bias[n];
                if (EPI == 2) vv += res[(size_t)m * ldc + n];
                if (EPI == 3) vv = vv / (1.0f + expf(-vv));
                C[(size_t)m * ldc + n] = vv;
            }
        }
    }
}

// ---------------- small SIMT GEMM (pos projections, M=64) ---------------------
#define TK 16
#define TPAD 68
__global__ void gemm_tn_small_kernel(const float* __restrict__ A, int lda,
                                     const float* __restrict__ W, int ldw,
                                     const float* __restrict__ bias,
                                     float* __restrict__ C, int ldc, int Kd) {
    int m0 = blockIdx.y * 64, n0 = blockIdx.x * 64;
    __shared__ float As[TK][TPAD];
    __shared__ float Ws2[TK][TPAD];
    const int tid = threadIdx.x;
    const int tx = tid & 15, ty = tid >> 4;
    const int lk = tid & 15, lm = tid >> 4;
    float acc[4][4] = {};
    for (int k0 = 0; k0 < Kd; k0 += TK) {
        #pragma unroll
        for (int r = 0; r < 4; r++) {
            As[lk][lm + 16 * r]  = A[(size_t)(m0 + lm + 16 * r) * lda + k0 + lk];
            Ws2[lk][lm + 16 * r] = W[(size_t)(n0 + lm + 16 * r) * ldw + k0 + lk];
        }
        __syncthreads();
        #pragma unroll
        for (int kk = 0; kk < TK; kk++) {
            float4 a = *(const float4*)&As[kk][ty * 4];
            float4 b = *(const float4*)&Ws2[kk][tx * 4];
            float av[4] = {a.x, a.y, a.z, a.w};
            float bv[4] = {b.x, b.y, b.z, b.w};
            #pragma unroll
            for (int i = 0; i < 4; i++)
                #pragma unroll
                for (int j = 0; j < 4; j++)
                    acc[i][j] += av[i] * bv[j];
        }
        __syncthreads();
    }
    #pragma unroll
    for (int i = 0; i < 4; i++) {
        int m = m0 + ty * 4 + i;
        #pragma unroll
        for (int j = 0; j < 4; j++) {
            int n = n0 + tx * 4 + j;
            C[(size_t)m * ldc + n] = acc[i][j] + bias[n];
        }
    }
}

// =========================== fused flash attention =============================
// One CTA per (z = b*H+h, i-tile of 128). 8 warps; warp w owns rows [w*16, w*16+16).
// Loop over 8 j-tiles of 128: S = Q K^T (mma) + disentangled bias (LDG gathers),
// online softmax in registers, P staged in smem, O += P V (mma).
// smem: Kb[128][68] | Vb[64][132] | Pb[128][132]  (Pb doubles as Q staging)
#define KST 68
#define PST 132
#define FA_SMEM ((128*KST + 64*PST + 128*PST) * 4)

__global__ void __launch_bounds__(256, 1) flash_attn_kernel(
    const float* __restrict__ qg, const float* __restrict__ kg,
    const float* __restrict__ vt,
    const float* __restrict__ c2p, const float* __restrict__ p2c,
    const int* __restrict__ lut, float* __restrict__ ctx)
{
    extern __shared__ float sm[];
    float* Kb = sm;                        // 128 x 68
    float* Vb = sm + 128*KST;              // 64 x 132
    float* Pb = sm + 128*KST + 64*PST;     // 128 x 132 (and Q stage @ stride 68)

    const int tid = threadIdx.x, w = tid >> 5, lane = tid & 31;
    const int g = lane >> 2, tg = lane & 3;
    const int z = blockIdx.z, bb = z >> 3, hh = z & 7;
    const int i0 = blockIdx.x * 128;

    const float* c2pz = c2p + (size_t)z * Ssz * NPOS;
    const float* p2cz = p2c + (size_t)z * Ssz * NPOS;

    const uint32_t sK = (uint32_t)__cvta_generic_to_shared(Kb);
    const uint32_t sV = (uint32_t)__cvta_generic_to_shared(Vb);
    const uint32_t sP = (uint32_t)__cvta_generic_to_shared(Pb);

    // loaders: K tile (128 rows x 64 d), V tile (64 rows x 128 j), Q tile like K
    auto loadK = [&](int jt) {
        int j0 = jt * 128;
        #pragma unroll
        for (int c = 0; c < 8; c++) {
            int id = tid * 8 + c;
            int row = id >> 4, fcol = (id & 15) * 4;
            CP_ASYNC16(sK + (uint32_t)(row * KST + fcol) * 4u,
                       kg + ((size_t)bb * Ssz + j0 + row) * Dsz + hh * DHsz + fcol);
        }
        CP_COMMIT();
    };
    auto loadV = [&](int jt) {
        int j0 = jt * 128;
        #pragma unroll
        for (int c = 0; c < 8; c++) {
            int id = tid * 8 + c;
            int row = id >> 5, fcol = (id & 31) * 4;
            CP_ASYNC16(sV + (uint32_t)(row * PST + fcol) * 4u,
                       vt + ((size_t)bb * Dsz + hh * DHsz + row) * Ssz + j0 + fcol);
        }
        CP_COMMIT();
    };

    // prologue: Q -> Pb (stride 68), then K0, V0
    #pragma unroll
    for (int c = 0; c < 8; c++) {
        int id = tid * 8 + c;
        int row = id >> 4, fcol = (id & 15) * 4;
        CP_ASYNC16(sP + (uint32_t)(row * KST + fcol) * 4u,
                   qg + ((size_t)bb * Ssz + i0 + row) * Dsz + hh * DHsz + fcol);
    }
    CP_COMMIT();
    loadK(0);
    loadV(0);

    CP_WAIT2();          // Q done
    __syncthreads();

    // Q fragments -> registers (8 k-chunks x 4 regs)
    uint32_t qf[8][4];
    #pragma unroll
    for (int kc = 0; kc < 8; kc++) {
        const uint32_t* p = (const uint32_t*)&Pb[(w * 16 + g) * KST + kc * 8 + tg];
        qf[kc][0] = p[0];
        qf[kc][1] = p[8 * KST];
        qf[kc][2] = p[4];
        qf[kc][3] = p[8 * KST + 4];
    }

    float acc_o[8][4] = {};
    float m_r[2] = {-1e30f, -1e30f};
    float l_r[2] = {0.f, 0.f};
    const float SCALE = 0.07216878364870323f;  // 1/sqrt(64*3)
    const int mg0 = i0 + w * 16 + g;           // global row (and +8)

    for (int jt = 0; jt < 8; jt++) {
        const int j0 = jt * 128;
        CP_WAIT1();          // K_jt arrived (V_jt may pend)
        __syncthreads();

        // ---- S = Q K^T ----
        float acc_s[16][4] = {};
        #pragma unroll
        for (int kc = 0; kc < 8; kc++) {
            #pragma unroll
            for (int in = 0; in < 16; in++) {
                uint32_t bf[2];
                const uint32_t* p = (const uint32_t*)&Kb[(in * 8 + g) * KST + kc * 8 + tg];
                bf[0] = p[0]; bf[1] = p[4];
                mma_tf32(acc_s[in], qf[kc], bf);
            }
        }

        // ---- bias + online softmax (registers) ----
        float mx0 = -1e30f, mx1 = -1e30f;
        #pragma unroll
        for (int in = 0; in < 16; in++) {
            int nbase = j0 + in * 8 + tg * 2;
            #pragma unroll
            for (int e = 0; e < 4; e++) {
                int m = mg0 + ((e >= 2) ? 8 : 0);
                int n = nbase + (e & 1);
                int idx = __ldg(&lut[m - n + (Ssz - 1)]);
                float vv = (acc_s[in][e] + __ldg(&c2pz[(size_t)m * NPOS + idx])
                                         + __ldg(&p2cz[(size_t)n * NPOS + idx])) * SCALE;
                acc_s[in][e] = vv;
                if (e < 2) mx0 = fmaxf(mx0, vv); else mx1 = fmaxf(mx1, vv);
            }
        }
        mx0 = fmaxf(mx0, __shfl_xor_sync(0xffffffffu, mx0, 1));
        mx0 = fmaxf(mx0, __shfl_xor_sync(0xffffffffu, mx0, 2));
        mx1 = fmaxf(mx1, __shfl_xor_sync(0xffffffffu, mx1, 1));
        mx1 = fmaxf(mx1, __shfl_xor_sync(0xffffffffu, mx1, 2));
        float mn0 = fmaxf(m_r[0], mx0), mn1 = fmaxf(m_r[1], mx1);
        float al0 = __expf(m_r[0] - mn0), al1 = __expf(m_r[1] - mn1);
        float s0 = 0.f, s1 = 0.f;
        #pragma unroll
        for (int in = 0; in < 16; in++) {
            float p0 = __expf(acc_s[in][0] - mn0);
            float p1 = __expf(acc_s[in][1] - mn0);
            float p2 = __expf(acc_s[in][2] - mn1);
            float p3 = __expf(acc_s[in][3] - mn1);
            acc_s[in][0] = p0; acc_s[in][1] = p1; acc_s[in][2] = p2; acc_s[in][3] = p3;
            s0 += p0 + p1; s1 += p2 + p3;
        }
        l_r[0] = l_r[0] * al0 + s0;
        l_r[1] = l_r[1] * al1 + s1;
        m_r[0] = mn0; m_r[1] = mn1;
        #pragma unroll
        for (int nf = 0; nf < 8; nf++) {
            acc_o[nf][0] *= al0; acc_o[nf][1] *= al0;
            acc_o[nf][2] *= al1; acc_o[nf][3] *= al1;
        }

        __syncthreads();     // Kb free; Pb free (prev O-gemm done; Q frags read)
        if (jt < 7) loadK(jt + 1);

        // ---- store P ----
        #pragma unroll
        for (int in = 0; in < 16; in++) {
            int col = in * 8 + tg * 2;
            *(float2*)&Pb[(w * 16 + g)     * PST + col] = make_float2(acc_s[in][0], acc_s[in][1]);
            *(float2*)&Pb[(w * 16 + g + 8) * PST + col] = make_float2(acc_s[in][2], acc_s[in][3]);
        }
        if (jt < 7) { CP_WAIT1(); } else { CP_WAIT0(); }  // V_jt arrived
        __syncthreads();

        // ---- O += P V ----
        #pragma unroll
        for (int kc2 = 0; kc2 < 16; kc2++) {
            uint32_t af[4];
            const uint32_t* pa = (const uint32_t*)&Pb[(w * 16 + g) * PST + kc2 * 8 + tg];
            af[0] = pa[0];
            af[1] = pa[8 * PST];
            af[2] = pa[4];
            af[3] = pa[8 * PST + 4];
            #pragma unroll
            for (int nf = 0; nf < 8; nf++) {
                uint32_t bf[2];
                const uint32_t* pb = (const uint32_t*)&Vb[(nf * 8 + g) * PST + kc2 * 8 + tg];
                bf[0] = pb[0]; bf[1] = pb[4];
                mma_tf32(acc_o[nf], af, bf);
            }
        }
        __syncthreads();     // Vb free
        if (jt < 7) loadV(jt + 1);
    }

    // ---- finalize: divide by l, write ctx[b, m, h*64+d] ----
    float l0 = l_r[0];
    l0 += __shfl_xor_sync(0xffffffffu, l0, 1);
    l0 += __shfl_xor_sync(0xffffffffu, l0, 2);
    float l1 = l_r[1];
    l1 += __shfl_xor_sync(0xffffffffu, l1, 1);
    l1 += __shfl_xor_sync(0xffffffffu, l1, 2);
    float inv0 = 1.0f / l0, inv1 = 1.0f / l1;
    float* c0 = ctx + ((size_t)bb * Ssz + mg0)     * Dsz + hh * DHsz;
    float* c1 = ctx + ((size_t)bb * Ssz + mg0 + 8) * Dsz + hh * DHsz;
    #pragma unroll
    for (int nf = 0; nf < 8; nf++) {
        int col = nf * 8 + tg * 2;
        *(float2*)&c0[col] = make_float2(acc_o[nf][0] * inv0, acc_o[nf][1] * inv0);
        *(float2*)&c1[col] = make_float2(acc_o[nf][2] * inv1, acc_o[nf][3] * inv1);
    }
}

// =============================== launch ========================================
extern "C" void kernel_launch(void* const* d_in, const int* in_sizes, int n_in,
                              void* d_out, int out_size) {
    const float* x      = (const float*)d_in[0];
    const float* ln1g   = (const float*)d_in[1];
    const float* ln1b   = (const float*)d_in[2];
    const float* dww    = (const float*)d_in[3];
    const float* dwb    = (const float*)d_in[4];
    const float* pww    = (const float*)d_in[5];
    const float* pwb    = (const float*)d_in[6];
    const float* ln2g   = (const float*)d_in[7];
    const float* ln2b   = (const float*)d_in[8];
    const float* qw     = (const float*)d_in[9];
    const float* qb     = (const float*)d_in[10];
    const float* kw     = (const float*)d_in[11];
    const float* kb     = (const float*)d_in[12];
    const float* vw     = (const float*)d_in[13];
    const float* vb     = (const float*)d_in[14];
    const float* ow     = (const float*)d_in[15];
    const float* ob     = (const float*)d_in[16];
    const float* relemb = (const float*)d_in[17];
    const float* ln3g   = (const float*)d_in[18];
    const float* ln3b   = (const float*)d_in[19];
    const float* w1     = (const float*)d_in[20];
    const float* b1     = (const float*)d_in[21];
    const float* w2     = (const float*)d_in[22];
    const float* b2     = (const float*)d_in[23];
    float* out = (float*)d_out;

    float *xn, *conv, *x1, *x2, *q, *k, *v, *vt, *ctx, *posk, *posq, *c2p, *p2c, *ff;
    int* lut;
    cudaGetSymbolAddress((void**)&xn,   g_xn);
    cudaGetSymbolAddress((void**)&conv, g_conv);
    cudaGetSymbolAddress((void**)&x1,   g_x1);
    cudaGetSymbolAddress((void**)&x2,   g_x2);
    cudaGetSymbolAddress((void**)&q,    g_q);
    cudaGetSymbolAddress((void**)&k,    g_k);
    cudaGetSymbolAddress((void**)&v,    g_v);
    cudaGetSymbolAddress((void**)&vt,   g_vt);
    cudaGetSymbolAddress((void**)&ctx,  g_ctx);
    cudaGetSymbolAddress((void**)&posk, g_posk);
    cudaGetSymbolAddress((void**)&posq, g_posq);
    cudaGetSymbolAddress((void**)&c2p,  g_c2p);
    cudaGetSymbolAddress((void**)&p2c,  g_p2c);
    cudaGetSymbolAddress((void**)&ff,   g_ff);
    cudaGetSymbolAddress((void**)&lut,  g_lut);

    static int smem_set = 0;
    if (!smem_set) {
        cudaFuncSetAttribute(flash_attn_kernel,
                             cudaFuncAttributeMaxDynamicSharedMemorySize, FA_SMEM);
        smem_set = 1;
    }

    build_lut_kernel<<<8, 256>>>(lut);

    // ---- conv block ----
    layernorm_kernel<<<NROWS, 256>>>(x, ln1g, ln1b, xn);
    dwconv_silu_kernel<<<(Bsz*Ssz*Dsz + 255) / 256, 256>>>(xn, dww, dwb, conv);
    gemm_mma_kernel<128,2,0><<<dim3(Dsz/128, NROWS/128, 1), 256>>>(
        conv, Dsz, pww, Dsz, pwb, x, x1, Dsz, Dsz);

    // ---- attention block ----
    layernorm_kernel<<<NROWS, 256>>>(x1, ln2g, ln2b, xn);
    gemm_mma_kernel<128,1,0><<<dim3(Dsz/128, NROWS/128, 1), 256>>>(
        xn, Dsz, qw, Dsz, qb, nullptr, q, Dsz, Dsz);
    gemm_mma_kernel<128,1,0><<<dim3(Dsz/128, NROWS/128, 1), 256>>>(
        xn, Dsz, kw, Dsz, kb, nullptr, k, Dsz, Dsz);
    gemm_mma_kernel<128,1,0><<<dim3(Dsz/128, NROWS/128, 1), 256>>>(
        xn, Dsz, vw, Dsz, vb, nullptr, v, Dsz, Dsz);
    transpose_v_kernel<<<dim3(Ssz/32, Dsz/32, Bsz), dim3(32, 8)>>>(v, vt);

    gemm_tn_small_kernel<<<dim3(Dsz/64, 1), 256>>>(relemb, Dsz, kw, Dsz, kb, posk, Dsz, Dsz);
    gemm_tn_small_kernel<<<dim3(Dsz/64, 1), 256>>>(relemb, Dsz, qw, Dsz, qb, posq, Dsz, Dsz);

    gemm_mma_kernel<64,0,3><<<dim3(1, Ssz/128, Bsz*Hsz), 256>>>(
        q, Dsz, posk, Dsz, nullptr, nullptr, c2p, NPOS, DHsz);
    gemm_mma_kernel<64,0,3><<<dim3(1, Ssz/128, Bsz*Hsz), 256>>>(
        k, Dsz, posq, Dsz, nullptr, nullptr, p2c, NPOS, DHsz);

    // fused scores + bias + softmax + ctx
    flash_attn_kernel<<<dim3(Ssz/128, 1, Bsz*Hsz), 256, FA_SMEM>>>(
        q, k, vt, c2p, p2c, lut, ctx);

    gemm_mma_kernel<128,2,0><<<dim3(Dsz/128, NROWS/128, 1), 256>>>(
        ctx, Dsz, ow, Dsz, ob, x1, x2, Dsz, Dsz);

    // ---- FFN block ----
    layernorm_kernel<<<NROWS, 256>>>(x2, ln3g, ln3b, xn);
    gemm_mma_kernel<128,3,0><<<dim3(FFsz/128, NROWS/128, 1), 256>>>(
        xn, Dsz, w1, Dsz, b1, nullptr, ff, FFsz, Dsz);
    gemm_mma_kernel<128,2,0><<<dim3(Dsz/128, NROWS/128, 1), 256>>>(
        ff, FFsz, w2, FFsz, b2, x2, out, Dsz, FFsz);
}

// round 4
// speedup vs baseline: 2.6275x; 1.0687x over previous
#include <cuda_runtime.h>
#include <math.h>
#include <stdint.h>

#define Bsz 8
#define Ssz 1024
#define Dsz 512
#define Hsz 8
#define DHsz 64
#define FFsz 1024
#define NPOS 64          // 2*SPAN
#define NROWS (Bsz*Ssz)  // 8192

// ---------------- scratch (device globals; no allocation allowed) ------------
__device__ float g_xn  [Bsz*Ssz*Dsz];
__device__ float g_conv[Bsz*Ssz*Dsz];
__device__ float g_x1  [Bsz*Ssz*Dsz];
__device__ float g_x2  [Bsz*Ssz*Dsz];
__device__ float g_q   [Bsz*Ssz*Dsz];
__device__ float g_k   [Bsz*Ssz*Dsz];
__device__ float g_v   [Bsz*Ssz*Dsz];
__device__ float g_vt  [Bsz*Ssz*Dsz];   // [B, D, S]
__device__ float g_ctx [Bsz*Ssz*Dsz];
__device__ float g_posk[NPOS*Dsz];
__device__ float g_posq[NPOS*Dsz];
__device__ float g_c2p [Bsz*Hsz*Ssz*NPOS];
__device__ float g_p2c [Bsz*Hsz*Ssz*NPOS];
__device__ float g_ff  [Bsz*Ssz*FFsz];
__device__ int   g_lut [2*Ssz];

// ---------------- relative-position bucket LUT --------------------------------
__global__ void build_lut_kernel(int* __restrict__ lut) {
    int t = blockIdx.x * blockDim.x + threadIdx.x;
    if (t >= 2*Ssz - 1) return;
    int rel = t - (Ssz - 1);   // i - j
    const int mid = 16;        // BUCKETS/2
    int bucket;
    if (rel > -mid && rel < mid) {
        bucket = rel;
    } else {
        float absp = fabsf((float)rel);
        if (absp <= (float)mid) {
            bucket = rel;
        } else {
            float logp = ceilf(logf(absp / 16.0f) / logf(127.0f / 16.0f) * 15.0f) + 16.0f;
            bucket = (rel > 0 ? 1 : -1) * (int)logp;
        }
    }
    int idx = bucket + 32;
    idx = min(max(idx, 0), 63);
    lut[t] = idx;
}

// ---------------- LayerNorm (D=512, one block per row) ------------------------
__global__ void layernorm_kernel(const float* __restrict__ x,
                                 const float* __restrict__ g,
                                 const float* __restrict__ bb,
                                 float* __restrict__ out) {
    const float* xr = x + (size_t)blockIdx.x * Dsz;
    float* orow = out + (size_t)blockIdx.x * Dsz;
    int tid = threadIdx.x;  // 256
    float v0 = xr[tid], v1 = xr[tid + 256];
    float s = v0 + v1, ss = v0 * v0 + v1 * v1;
    __shared__ float r1[8], r2[8];
    #pragma unroll
    for (int o = 16; o; o >>= 1) {
        s  += __shfl_xor_sync(0xffffffffu, s, o);
        ss += __shfl_xor_sync(0xffffffffu, ss, o);
    }
    if ((tid & 31) == 0) { r1[tid >> 5] = s; r2[tid >> 5] = ss; }
    __syncthreads();
    float S1 = 0.f, S2 = 0.f;
    #pragma unroll
    for (int i = 0; i < 8; i++) { S1 += r1[i]; S2 += r2[i]; }
    float mean = S1 * (1.0f / Dsz);
    float var  = S2 * (1.0f / Dsz) - mean * mean;
    float rs = rsqrtf(var + 1e-5f);
    orow[tid]       = (v0 - mean) * rs * g[tid]       + bb[tid];
    orow[tid + 256] = (v1 - mean) * rs * g[tid + 256] + bb[tid + 256];
}

// ---------------- depthwise conv (K=3 along S) + bias + SiLU ------------------
__global__ void dwconv_silu_kernel(const float* __restrict__ xn,
                                   const float* __restrict__ w,
                                   const float* __restrict__ bias,
                                   float* __restrict__ out) {
    size_t idx = (size_t)blockIdx.x * blockDim.x + threadIdx.x;
    if (idx >= (size_t)Bsz * Ssz * Dsz) return;
    int d = (int)(idx % Dsz);
    int s = (int)((idx / Dsz) % Ssz);
    const float* base = xn + idx;
    float w0 = w[d * 3 + 0], w1 = w[d * 3 + 1], w2 = w[d * 3 + 2];
    float acc = bias[d] + base[0] * w1;
    if (s > 0)        acc += base[-Dsz] * w0;
    if (s < Ssz - 1)  acc += base[ Dsz] * w2;
    out[idx] = acc / (1.0f + expf(-acc));  // silu
}

// ---------------- V transpose: [B,S,D] -> [B,D,S] ------------------------------
__global__ void transpose_v_kernel(const float* __restrict__ v, float* __restrict__ vt) {
    __shared__ float tile[32][33];
    int b = blockIdx.z;
    int s0 = blockIdx.x * 32, d0 = blockIdx.y * 32;
    int tx = threadIdx.x, ty = threadIdx.y;  // 32 x 8
    #pragma unroll
    for (int j = 0; j < 32; j += 8)
        tile[ty + j][tx] = v[((size_t)b * Ssz + s0 + ty + j) * Dsz + d0 + tx];
    __syncthreads();
    #pragma unroll
    for (int j = 0; j < 32; j += 8)
        vt[((size_t)b * Dsz + d0 + ty + j) * Ssz + s0 + tx] = tile[tx][ty + j];
}

// ---------------- mma.tf32 + ldmatrix helpers ----------------------------------
__device__ __forceinline__ void mma_tf32(float c[4], const uint32_t a[4], const uint32_t b[2]) {
    asm volatile(
        "mma.sync.aligned.m16n8k8.row.col.f32.tf32.tf32.f32 "
        "{%0,%1,%2,%3}, {%4,%5,%6,%7}, {%8,%9}, {%0,%1,%2,%3};"
        : "+f"(c[0]), "+f"(c[1]), "+f"(c[2]), "+f"(c[3])
        : "r"(a[0]), "r"(a[1]), "r"(a[2]), "r"(a[3]), "r"(b[0]), "r"(b[1]));
}

// ldmatrix: 4x (8 rows x 16B). For tf32, one 8x4-tf32 tile per matrix; gives
// exactly the m16n8k8 tf32 fragment layout.
__device__ __forceinline__ void ldsm_x4(uint32_t r[4], uint32_t addr) {
    asm volatile("ldmatrix.sync.aligned.m8n8.x4.shared.b16 {%0,%1,%2,%3}, [%4];"
                 : "=r"(r[0]), "=r"(r[1]), "=r"(r[2]), "=r"(r[3]) : "r"(addr));
}

#define CP_ASYNC16(dst_u32, src_ptr) \
    asm volatile("cp.async.ca.shared.global [%0], [%1], 16;" :: "r"(dst_u32), "l"(src_ptr))
#define CP_COMMIT() asm volatile("cp.async.commit_group;")
#define CP_WAIT2()  asm volatile("cp.async.wait_group 2;")
#define CP_WAIT1()  asm volatile("cp.async.wait_group 1;")
#define CP_WAIT0()  asm volatile("cp.async.wait_group 0;")

// ---------------- tensor-core TN GEMM -------------------------------------------
// C[m,n] = sum_k A[m,k] * W[n,k]
// EPI: 0 none, 1 +bias, 2 +bias+res, 3 silu(+bias)
// MODE: 0 plain, 3 pos-merged (z<64: q.posk -> c2p ; z>=64: k.posq -> p2c),
//       4 qkv-merged (z selects {qw,kw,vw})
#define SSTRIDE 20

template<int CN, int EPI, int MODE>
__global__ void __launch_bounds__(256, 2) gemm_mma_kernel(
    const float* __restrict__ A0, int lda,
    const float* __restrict__ W0, int ldw,
    const float* __restrict__ bias0, const float* __restrict__ res,
    float* __restrict__ C0, int ldc, int K,
    const float* __restrict__ Aa, const float* __restrict__ Wa,
    const float* __restrict__ Wb2, const float* __restrict__ ba,
    const float* __restrict__ bb2, float* __restrict__ Ca, float* __restrict__ Cb)
{
    constexpr int NWN = CN / 32;     // warps along N
    constexpr int NWM = 8 / NWN;     // warps along M
    constexpr int MT  = 8 / NWM;     // m16 tiles per warp

    __shared__ float As[2][128 * SSTRIDE];
    __shared__ float Ws[2][CN  * SSTRIDE];

    const int tid  = threadIdx.x;
    const int wid  = tid >> 5, lane = tid & 31;
    const int g    = lane >> 2, tg = lane & 3;
    const int wm   = wid % NWM, wn = wid / NWM;

    const int z = blockIdx.z;
    const float* A = A0; const float* W = W0; float* C = C0;
    const float* bias = bias0;
    if (MODE == 3) {
        int zz = z & 63, sel = z >> 6;
        int bb = zz >> 3, hh = zz & 7;
        A = (sel ? Aa : A0) + (size_t)bb * Ssz * Dsz + hh * DHsz;
        W = (sel ? Wa : W0) + hh * DHsz;
        C = (sel ? Ca : C0) + (size_t)zz * Ssz * NPOS;
    } else if (MODE == 4) {
        W    = (z == 0) ? W0 : (z == 1 ? Wa : Wb2);
        bias = (z == 0) ? bias0 : (z == 1 ? ba : bb2);
        C    = (z == 0) ? C0 : (z == 1 ? Ca : Cb);
    }

    const int m_cta = blockIdx.y * 128, n_cta = blockIdx.x * CN;

    const uint32_t sA = (uint32_t)__cvta_generic_to_shared(&As[0][0]);
    const uint32_t sW = (uint32_t)__cvta_generic_to_shared(&Ws[0][0]);

    const int qd = (tid & 3) * 4;
    const int rr = tid >> 2;

    auto fetch = [&](int t, int buf) {
        int k0 = t * 16;
        #pragma unroll
        for (int r = 0; r < 2; r++) {
            int row = rr + 64 * r;
            uint32_t d = sA + (uint32_t)(buf * 128 * SSTRIDE + row * SSTRIDE + qd) * 4u;
            CP_ASYNC16(d, A + (size_t)(m_cta + row) * lda + k0 + qd);
        }
        #pragma unroll
        for (int r = 0; r < CN / 64; r++) {
            int row = rr + 64 * r;
            uint32_t d = sW + (uint32_t)(buf * CN * SSTRIDE + row * SSTRIDE + qd) * 4u;
            CP_ASYNC16(d, W + (size_t)(n_cta + row) * ldw + k0 + qd);
        }
        CP_COMMIT();
    };

    // ldmatrix per-thread offsets (float units)
    const int lq = lane >> 3, lr = lane & 7;
    const int aoff = ((lq & 1) * 8 + lr) * SSTRIDE + (lq >> 1) * 4;  // A frag
    const int boff = ((lq >> 1) * 8 + lr) * SSTRIDE + (lq & 1) * 4;  // B frag pair

    float acc[MT][4][4] = {};

    const int T = K / 16;
    fetch(0, 0);
    for (int it = 0; it < T; it++) {
        if (it + 1 < T) { fetch(it + 1, (it + 1) & 1); CP_WAIT1(); }
        else            { CP_WAIT0(); }
        __syncthreads();
        const uint32_t bA = sA + (uint32_t)((it & 1) * 128 * SSTRIDE) * 4u;
        const uint32_t bW = sW + (uint32_t)((it & 1) * CN  * SSTRIDE) * 4u;
        #pragma unroll
        for (int ks = 0; ks < 2; ks++) {
            const int kk = ks * 8;
            uint32_t af[MT][4];
            #pragma unroll
            for (int im = 0; im < MT; im++)
                ldsm_x4(af[im], bA + (uint32_t)((wm * MT * 16 + im * 16) * SSTRIDE + aoff + kk) * 4u);
            uint32_t bf[2][4];   // each covers 2 n8-tiles
            #pragma unroll
            for (int ip = 0; ip < 2; ip++)
                ldsm_x4(bf[ip], bW + (uint32_t)((wn * 32 + ip * 16) * SSTRIDE + boff + kk) * 4u);
            #pragma unroll
            for (int im = 0; im < MT; im++)
                #pragma unroll
                for (int in = 0; in < 4; in++)
                    mma_tf32(acc[im][in], af[im], &bf[in >> 1][(in & 1) * 2]);
        }
        __syncthreads();
    }

    #pragma unroll
    for (int im = 0; im < MT; im++) {
        int mrow0 = m_cta + wm * MT * 16 + im * 16 + g;
        #pragma unroll
        for (int in = 0; in < 4; in++) {
            int ncol0 = n_cta + wn * 32 + in * 8 + tg * 2;
            #pragma unroll
            for (int e = 0; e < 4; e++) {
                int m = mrow0 + ((e >= 2) ? 8 : 0);
                int n = ncol0 + (e & 1);
                float vv = acc[im][in][e];
                if (EPI == 1 || EPI == 2 || EPI == 3) vv += bias[n];
                if (EPI == 2) vv += res[(size_t)m * ldc + n];
                if (EPI == 3) vv = vv / (1.0f + expf(-vv));
                C[(size_t)m * ldc + n] = vv;
            }
        }
    }
}

// ---------------- small SIMT GEMM (pos projections, M=64) ---------------------
#define TK 16
#define TPAD 68
__global__ void gemm_tn_small_kernel(const float* __restrict__ A, int lda,
                                     const float* __restrict__ W, int ldw,
                                     const float* __restrict__ bias,
                                     float* __restrict__ C, int ldc, int Kd) {
    int m0 = blockIdx.y * 64, n0 = blockIdx.x * 64;
    __shared__ float As[TK][TPAD];
    __shared__ float Ws2[TK][TPAD];
    const int tid = threadIdx.x;
    const int tx = tid & 15, ty = tid >> 4;
    const int lk = tid & 15, lm = tid >> 4;
    float acc[4][4] = {};
    for (int k0 = 0; k0 < Kd; k0 += TK) {
        #pragma unroll
        for (int r = 0; r < 4; r++) {
            As[lk][lm + 16 * r]  = A[(size_t)(m0 + lm + 16 * r) * lda + k0 + lk];
            Ws2[lk][lm + 16 * r] = W[(size_t)(n0 + lm + 16 * r) * ldw + k0 + lk];
        }
        __syncthreads();
        #pragma unroll
        for (int kk = 0; kk < TK; kk++) {
            float4 a = *(const float4*)&As[kk][ty * 4];
            float4 b = *(const float4*)&Ws2[kk][tx * 4];
            float av[4] = {a.x, a.y, a.z, a.w};
            float bv[4] = {b.x, b.y, b.z, b.w};
            #pragma unroll
            for (int i = 0; i < 4; i++)
                #pragma unroll
                for (int j = 0; j < 4; j++)
                    acc[i][j] += av[i] * bv[j];
        }
        __syncthreads();
    }
    #pragma unroll
    for (int i = 0; i < 4; i++) {
        int m = m0 + ty * 4 + i;
        #pragma unroll
        for (int j = 0; j < 4; j++) {
            int n = n0 + tx * 4 + j;
            C[(size_t)m * ldc + n] = acc[i][j] + bias[n];
        }
    }
}

// =========================== fused flash attention =============================
// One CTA per (z = b*H+h, i-tile of 128). 8 warps; warp w owns rows [w*16, w*16+16).
#define KST 68
#define PST 132
#define FA_SMEM ((128*KST + 64*PST + 128*PST) * 4)

__global__ void __launch_bounds__(256, 1) flash_attn_kernel(
    const float* __restrict__ qg, const float* __restrict__ kg,
    const float* __restrict__ vt,
    const float* __restrict__ c2p, const float* __restrict__ p2c,
    const int* __restrict__ lut, float* __restrict__ ctx)
{
    extern __shared__ float sm[];
    float* Kb = sm;                        // 128 x 68
    float* Vb = sm + 128*KST;              // 64 x 132
    float* Pb = sm + 128*KST + 64*PST;     // 128 x 132 (and Q stage @ stride 68)

    const int tid = threadIdx.x, w = tid >> 5, lane = tid & 31;
    const int g = lane >> 2, tg = lane & 3;
    const int z = blockIdx.z, bb = z >> 3, hh = z & 7;
    const int i0 = blockIdx.x * 128;

    const float* c2pz = c2p + (size_t)z * Ssz * NPOS;
    const float* p2cz = p2c + (size_t)z * Ssz * NPOS;

    const uint32_t sK = (uint32_t)__cvta_generic_to_shared(Kb);
    const uint32_t sV = (uint32_t)__cvta_generic_to_shared(Vb);
    const uint32_t sP = (uint32_t)__cvta_generic_to_shared(Pb);

    auto loadK = [&](int jt) {
        int j0 = jt * 128;
        #pragma unroll
        for (int c = 0; c < 8; c++) {
            int id = tid * 8 + c;
            int row = id >> 4, fcol = (id & 15) * 4;
            CP_ASYNC16(sK + (uint32_t)(row * KST + fcol) * 4u,
                       kg + ((size_t)bb * Ssz + j0 + row) * Dsz + hh * DHsz + fcol);
        }
        CP_COMMIT();
    };
    auto loadV = [&](int jt) {
        int j0 = jt * 128;
        #pragma unroll
        for (int c = 0; c < 8; c++) {
            int id = tid * 8 + c;
            int row = id >> 5, fcol = (id & 31) * 4;
            CP_ASYNC16(sV + (uint32_t)(row * PST + fcol) * 4u,
                       vt + ((size_t)bb * Dsz + hh * DHsz + row) * Ssz + j0 + fcol);
        }
        CP_COMMIT();
    };

    #pragma unroll
    for (int c = 0; c < 8; c++) {
        int id = tid * 8 + c;
        int row = id >> 4, fcol = (id & 15) * 4;
        CP_ASYNC16(sP + (uint32_t)(row * KST + fcol) * 4u,
                   qg + ((size_t)bb * Ssz + i0 + row) * Dsz + hh * DHsz + fcol);
    }
    CP_COMMIT();
    loadK(0);
    loadV(0);

    CP_WAIT2();          // Q done
    __syncthreads();

    // ldmatrix per-thread offsets
    const int lq = lane >> 3, lr = lane & 7;
    const int aoffQ = ((lq & 1) * 8 + lr) * KST + (lq >> 1) * 4;
    const int boffK = ((lq >> 1) * 8 + lr) * KST + (lq & 1) * 4;
    const int aoffP = ((lq & 1) * 8 + lr) * PST + (lq >> 1) * 4;
    const int boffV = ((lq >> 1) * 8 + lr) * PST + (lq & 1) * 4;

    // Q fragments -> registers (8 k-chunks x 4 regs) via ldmatrix
    uint32_t qf[8][4];
    #pragma unroll
    for (int kc = 0; kc < 8; kc++)
        ldsm_x4(qf[kc], sP + (uint32_t)((w * 16) * KST + aoffQ + kc * 8) * 4u);

    float acc_o[8][4] = {};
    float m_r[2] = {-1e30f, -1e30f};
    float l_r[2] = {0.f, 0.f};
    const float SCALE = 0.07216878364870323f;  // 1/sqrt(64*3)
    const int mg0 = i0 + w * 16 + g;

    for (int jt = 0; jt < 8; jt++) {
        const int j0 = jt * 128;
        CP_WAIT1();          // K_jt arrived
        __syncthreads();

        // ---- S = Q K^T ----
        float acc_s[16][4] = {};
        #pragma unroll
        for (int kc = 0; kc < 8; kc++) {
            #pragma unroll
            for (int ip = 0; ip < 8; ip++) {   // 8 ldsm pairs -> 16 n8-tiles
                uint32_t bf[4];
                ldsm_x4(bf, sK + (uint32_t)((ip * 16) * KST + boffK + kc * 8) * 4u);
                mma_tf32(acc_s[ip * 2],     qf[kc], &bf[0]);
                mma_tf32(acc_s[ip * 2 + 1], qf[kc], &bf[2]);
            }
        }

        // ---- bias + online softmax ----
        float mx0 = -1e30f, mx1 = -1e30f;
        #pragma unroll
        for (int in = 0; in < 16; in++) {
            int nbase = j0 + in * 8 + tg * 2;
            #pragma unroll
            for (int e = 0; e < 4; e++) {
                int m = mg0 + ((e >= 2) ? 8 : 0);
                int n = nbase + (e & 1);
                int idx = __ldg(&lut[m - n + (Ssz - 1)]);
                float vv = (acc_s[in][e] + __ldg(&c2pz[(size_t)m * NPOS + idx])
                                         + __ldg(&p2cz[(size_t)n * NPOS + idx])) * SCALE;
                acc_s[in][e] = vv;
                if (e < 2) mx0 = fmaxf(mx0, vv); else mx1 = fmaxf(mx1, vv);
            }
        }
        mx0 = fmaxf(mx0, __shfl_xor_sync(0xffffffffu, mx0, 1));
        mx0 = fmaxf(mx0, __shfl_xor_sync(0xffffffffu, mx0, 2));
        mx1 = fmaxf(mx1, __shfl_xor_sync(0xffffffffu, mx1, 1));
        mx1 = fmaxf(mx1, __shfl_xor_sync(0xffffffffu, mx1, 2));
        float mn0 = fmaxf(m_r[0], mx0), mn1 = fmaxf(m_r[1], mx1);
        float al0 = __expf(m_r[0] - mn0), al1 = __expf(m_r[1] - mn1);
        float s0 = 0.f, s1 = 0.f;
        #pragma unroll
        for (int in = 0; in < 16; in++) {
            float p0 = __expf(acc_s[in][0] - mn0);
            float p1 = __expf(acc_s[in][1] - mn0);
            float p2 = __expf(acc_s[in][2] - mn1);
            float p3 = __expf(acc_s[in][3] - mn1);
            acc_s[in][0] = p0; acc_s[in][1] = p1; acc_s[in][2] = p2; acc_s[in][3] = p3;
            s0 += p0 + p1; s1 += p2 + p3;
        }
        l_r[0] = l_r[0] * al0 + s0;
        l_r[1] = l_r[1] * al1 + s1;
        m_r[0] = mn0; m_r[1] = mn1;
        #pragma unroll
        for (int nf = 0; nf < 8; nf++) {
            acc_o[nf][0] *= al0; acc_o[nf][1] *= al0;
            acc_o[nf][2] *= al1; acc_o[nf][3] *= al1;
        }

        __syncthreads();     // Kb free; Pb free
        if (jt < 7) loadK(jt + 1);

        // ---- store P ----
        #pragma unroll
        for (int in = 0; in < 16; in++) {
            int col = in * 8 + tg * 2;
            *(float2*)&Pb[(w * 16 + g)     * PST + col] = make_float2(acc_s[in][0], acc_s[in][1]);
            *(float2*)&Pb[(w * 16 + g + 8) * PST + col] = make_float2(acc_s[in][2], acc_s[in][3]);
        }
        if (jt < 7) { CP_WAIT1(); } else { CP_WAIT0(); }  // V_jt arrived
        __syncthreads();

        // ---- O += P V ----
        #pragma unroll
        for (int kc2 = 0; kc2 < 16; kc2++) {
            uint32_t af[4];
            ldsm_x4(af, sP + (uint32_t)((w * 16) * PST + aoffP + kc2 * 8) * 4u);
            #pragma unroll
            for (int ip = 0; ip < 4; ip++) {
                uint32_t bf[4];
                ldsm_x4(bf, sV + (uint32_t)((ip * 16) * PST + boffV + kc2 * 8) * 4u);
                mma_tf32(acc_o[ip * 2],     af, &bf[0]);
                mma_tf32(acc_o[ip * 2 + 1], af, &bf[2]);
            }
        }
        __syncthreads();     // Vb free
        if (jt < 7) loadV(jt + 1);
    }

    // ---- finalize ----
    float l0 = l_r[0];
    l0 += __shfl_xor_sync(0xffffffffu, l0, 1);
    l0 += __shfl_xor_sync(0xffffffffu, l0, 2);
    float l1 = l_r[1];
    l1 += __shfl_xor_sync(0xffffffffu, l1, 1);
    l1 += __shfl_xor_sync(0xffffffffu, l1, 2);
    float inv0 = 1.0f / l0, inv1 = 1.0f / l1;
    float* c0 = ctx + ((size_t)bb * Ssz + mg0)     * Dsz + hh * DHsz;
    float* c1 = ctx + ((size_t)bb * Ssz + mg0 + 8) * Dsz + hh * DHsz;
    #pragma unroll
    for (int nf = 0; nf < 8; nf++) {
        int col = nf * 8 + tg * 2;
        *(float2*)&c0[col] = make_float2(acc_o[nf][0] * inv0, acc_o[nf][1] * inv0);
        *(float2*)&c1[col] = make_float2(acc_o[nf][2] * inv1, acc_o[nf][3] * inv1);
    }
}

// =============================== launch ========================================
extern "C" void kernel_launch(void* const* d_in, const int* in_sizes, int n_in,
                              void* d_out, int out_size) {
    const float* x      = (const float*)d_in[0];
    const float* ln1g   = (const float*)d_in[1];
    const float* ln1b   = (const float*)d_in[2];
    const float* dww    = (const float*)d_in[3];
    const float* dwb    = (const float*)d_in[4];
    const float* pww    = (const float*)d_in[5];
    const float* pwb    = (const float*)d_in[6];
    const float* ln2g   = (const float*)d_in[7];
    const float* ln2b   = (const float*)d_in[8];
    const float* qw     = (const float*)d_in[9];
    const float* qb     = (const float*)d_in[10];
    const float* kw     = (const float*)d_in[11];
    const float* kb     = (const float*)d_in[12];
    const float* vw     = (const float*)d_in[13];
    const float* vb     = (const float*)d_in[14];
    const float* ow     = (const float*)d_in[15];
    const float* ob     = (const float*)d_in[16];
    const float* relemb = (const float*)d_in[17];
    const float* ln3g   = (const float*)d_in[18];
    const float* ln3b   = (const float*)d_in[19];
    const float* w1     = (const float*)d_in[20];
    const float* b1     = (const float*)d_in[21];
    const float* w2     = (const float*)d_in[22];
    const float* b2     = (const float*)d_in[23];
    float* out = (float*)d_out;

    float *xn, *conv, *x1, *x2, *q, *k, *v, *vt, *ctx, *posk, *posq, *c2p, *p2c, *ff;
    int* lut;
    cudaGetSymbolAddress((void**)&xn,   g_xn);
    cudaGetSymbolAddress((void**)&conv, g_conv);
    cudaGetSymbolAddress((void**)&x1,   g_x1);
    cudaGetSymbolAddress((void**)&x2,   g_x2);
    cudaGetSymbolAddress((void**)&q,    g_q);
    cudaGetSymbolAddress((void**)&k,    g_k);
    cudaGetSymbolAddress((void**)&v,    g_v);
    cudaGetSymbolAddress((void**)&vt,   g_vt);
    cudaGetSymbolAddress((void**)&ctx,  g_ctx);
    cudaGetSymbolAddress((void**)&posk, g_posk);
    cudaGetSymbolAddress((void**)&posq, g_posq);
    cudaGetSymbolAddress((void**)&c2p,  g_c2p);
    cudaGetSymbolAddress((void**)&p2c,  g_p2c);
    cudaGetSymbolAddress((void**)&ff,   g_ff);
    cudaGetSymbolAddress((void**)&lut,  g_lut);

    static int smem_set = 0;
    if (!smem_set) {
        cudaFuncSetAttribute(flash_attn_kernel,
                             cudaFuncAttributeMaxDynamicSharedMemorySize, FA_SMEM);
        smem_set = 1;
    }

    build_lut_kernel<<<8, 256>>>(lut);

    // ---- conv block ----
    layernorm_kernel<<<NROWS, 256>>>(x, ln1g, ln1b, xn);
    dwconv_silu_kernel<<<(Bsz*Ssz*Dsz + 255) / 256, 256>>>(xn, dww, dwb, conv);
    gemm_mma_kernel<128,2,0><<<dim3(Dsz/128, NROWS/128, 1), 256>>>(
        conv, Dsz, pww, Dsz, pwb, x, x1, Dsz, Dsz,
        nullptr, nullptr, nullptr, nullptr, nullptr, nullptr, nullptr);

    // ---- attention block ----
    layernorm_kernel<<<NROWS, 256>>>(x1, ln2g, ln2b, xn);
    // merged q/k/v projections (z selects weight/bias/output)
    gemm_mma_kernel<128,1,4><<<dim3(Dsz/128, NROWS/128, 3), 256>>>(
        xn, Dsz, qw, Dsz, qb, nullptr, q, Dsz, Dsz,
        nullptr, kw, vw, kb, vb, k, v);
    transpose_v_kernel<<<dim3(Ssz/32, Dsz/32, Bsz), dim3(32, 8)>>>(v, vt);

    gemm_tn_small_kernel<<<dim3(Dsz/64, 1), 256>>>(relemb, Dsz, kw, Dsz, kb, posk, Dsz, Dsz);
    gemm_tn_small_kernel<<<dim3(Dsz/64, 1), 256>>>(relemb, Dsz, qw, Dsz, qb, posq, Dsz, Dsz);

    // merged c2p/p2c
    gemm_mma_kernel<64,0,3><<<dim3(1, Ssz/128, 2*Bsz*Hsz), 256>>>(
        q, Dsz, posk, Dsz, nullptr, nullptr, c2p, NPOS, DHsz,
        k, posq, nullptr, nullptr, nullptr, p2c, nullptr);

    // fused scores + bias + softmax + ctx
    flash_attn_kernel<<<dim3(Ssz/128, 1, Bsz*Hsz), 256, FA_SMEM>>>(
        q, k, vt, c2p, p2c, lut, ctx);

    gemm_mma_kernel<128,2,0><<<dim3(Dsz/128, NROWS/128, 1), 256>>>(
        ctx, Dsz, ow, Dsz, ob, x1, x2, Dsz, Dsz,
        nullptr, nullptr, nullptr, nullptr, nullptr, nullptr, nullptr);

    // ---- FFN block ----
    layernorm_kernel<<<NROWS, 256>>>(x2, ln3g, ln3b, xn);
    gemm_mma_kernel<128,3,0><<<dim3(FFsz/128, NROWS/128, 1), 256>>>(
        xn, Dsz, w1, Dsz, b1, nullptr, ff, FFsz, Dsz,
        nullptr, nullptr, nullptr, nullptr, nullptr, nullptr, nullptr);
    gemm_mma_kernel<128,2,0><<<dim3(Dsz/128, NROWS/128, 1), 256>>>(
        ff, FFsz, w2, FFsz, b2, x2, out, Dsz, FFsz,
        nullptr, nullptr, nullptr, nullptr, nullptr, nullptr, nullptr);
}